// round 14
// baseline (speedup 1.0000x reference)
#include <cuda_runtime.h>
#include <cuda_fp16.h>
#include <math.h>

#define BATCH 4
#define SEQ   4096
#define EMB   512

// Scratch (__device__ globals: sanctioned, no runtime allocation)
__device__ float g_s[(size_t)BATCH * SEQ * SEQ];                  // 256 MB scores
__device__ __half g_xqh[BATCH * SEQ * EMB], g_xql[BATCH * SEQ * EMB];
__device__ __half g_xkh[BATCH * SEQ * EMB], g_xkl[BATCH * SEQ * EMB];
__device__ __half g_xvh[BATCH * SEQ * EMB], g_xvl[BATCH * SEQ * EMB];
__device__ __half g_wqh[EMB * EMB], g_wql[EMB * EMB];
__device__ __half g_wkh[EMB * EMB], g_wkl[EMB * EMB];
__device__ __half g_wvh[EMB * EMB], g_wvl[EMB * EMB];
__device__ __half g_qh[BATCH * SEQ * EMB], g_ql[BATCH * SEQ * EMB];
__device__ __half g_kh[BATCH * SEQ * EMB], g_kl[BATCH * SEQ * EMB];
__device__ __half g_vt[BATCH * SEQ * EMB];                        // [b][e][s]
__device__ __half g_p [(size_t)BATCH * SEQ * SEQ];                // 128 MB attn

__device__ __forceinline__ unsigned packh(__half a, __half b) {
    return ((unsigned)__half_as_ushort(b) << 16) | __half_as_ushort(a);
}
__device__ __forceinline__ void cp16(unsigned dst, const void* src) {
    asm volatile("cp.async.cg.shared.global [%0], [%1], 16;" :: "r"(dst), "l"(src));
}

#define MMAH(aa, bb, mi, aj, bj)                                              \
    asm volatile(                                                             \
        "mma.sync.aligned.m16n8k16.row.col.f32.f16.f16.f32 "                  \
        "{%0,%1,%2,%3}, {%4,%5,%6,%7}, {%8,%9}, {%0,%1,%2,%3};"               \
        : "+f"(acc[mi][aj][0]), "+f"(acc[mi][aj][1]),                         \
          "+f"(acc[mi][aj][2]), "+f"(acc[mi][aj][3])                          \
        : "r"(aa[mi][0]), "r"(aa[mi][1]), "r"(aa[mi][2]), "r"(aa[mi][3]),     \
          "r"(bb[bj][0]), "r"(bb[bj][1]))

// ---------------------------------------------------------------------------
// Elementwise fp32 -> split fp16 (h = rn(x), l = rn(x - h)), float4-wide.
// ---------------------------------------------------------------------------
__global__ void __launch_bounds__(256)
split_f32(const float* __restrict__ src, __half* __restrict__ H,
          __half* __restrict__ L, int n4)
{
    const int stride = gridDim.x * blockDim.x;
    for (int i = blockIdx.x * blockDim.x + threadIdx.x; i < n4; i += stride) {
        float4 v = reinterpret_cast<const float4*>(src)[i];
        __half h0 = __float2half_rn(v.x), h1 = __float2half_rn(v.y);
        __half h2 = __float2half_rn(v.z), h3 = __float2half_rn(v.w);
        __half l0 = __float2half_rn(v.x - __half2float(h0));
        __half l1 = __float2half_rn(v.y - __half2float(h1));
        __half l2 = __float2half_rn(v.z - __half2float(h2));
        __half l3 = __float2half_rn(v.w - __half2float(h3));
        reinterpret_cast<uint2*>(H)[i] = make_uint2(packh(h0, h1), packh(h2, h3));
        reinterpret_cast<uint2*>(L)[i] = make_uint2(packh(l0, l1), packh(l2, l3));
    }
}

// ===========================================================================
// h2 GEMM core: acc += (Ah+Al)[m,k] * (Bh+Bl)[n,k] over K.
// CTA tile 128(m)x64(n), BK=32, 256 threads (8 warps 4m x 2n), warp tile
// 32x32 (inner loop identical to validated rounds 11-13). cp.async double
// buffer, rows padded to 40 fp16. smem 61440 B -> 3 CTAs/SM, 24 warps/SM.
// EPI: 0 = fp32 C (score), 1 = split fp16 + bias (Q/K proj),
//      2 = transposed single fp16 + bias (V proj).
// ===========================================================================
#define H2TILE_A  10240                      // 128 * 40 * 2 bytes
#define H2TILE_N  5120                       // 64 * 40 * 2 bytes
#define H2STAGE_B (2 * (H2TILE_A + H2TILE_N))   // 30720
#define H2SMEM    (2 * H2STAGE_B)            // 61440 B -> 3 CTAs/SM

template <int EPI>
__global__ void __launch_bounds__(256)
gemm_h2(const __half* __restrict__ Ah, const __half* __restrict__ Al,
        const __half* __restrict__ Bh, const __half* __restrict__ Bl,
        const float* __restrict__ bias,
        float* __restrict__ Cf, __half* __restrict__ Ch, __half* __restrict__ Cl,
        int K, int lda, int ldb, int ldc,
        long sA, long sB, long sC)
{
    extern __shared__ unsigned su[];

    const int bz = blockIdx.z;
    Ah += (long)bz * sA; Al += (long)bz * sA;
    Bh += (long)bz * sB; Bl += (long)bz * sB;

    const int tid  = threadIdx.x;
    const int lane = tid & 31;
    const int wid  = tid >> 5;
    const int wm   = (wid & 3) * 32;
    const int wn   = (wid >> 2) * 32;        // 0 or 32
    const int m0   = blockIdx.y * 128;
    const int n0   = blockIdx.x * 64;

    unsigned smemU;
    asm("{ .reg .u64 t; cvta.to.shared.u64 t, %1; cvt.u32.u64 %0, t; }"
        : "=r"(smemU) : "l"(su));

    // cp.async mapping:
    //  A tile 128 rows x 4 chunks(16B) = 512 -> 2 chunks/thread
    //  B tile  64 rows x 4 chunks      = 256 -> 1 chunk/thread
    const int arow = tid >> 1;               // 0..127
    const int ac0  = (tid & 1) * 2;          // chunk base 0 or 2
    const int brow = tid >> 2;               // 0..63
    const int bch  = tid & 3;                // chunk 0..3

    auto stageCopy = [&](int buf, int kt) {
        const unsigned base = smemU + (unsigned)buf * H2STAGE_B;
        const long ao = (long)(m0 + arow) * lda + (long)kt * 32;
        const long bo = (long)(n0 + brow) * ldb + (long)kt * 32 + bch * 8;
        const unsigned bd = (unsigned)(brow * 80 + bch * 16);
#pragma unroll
        for (int i = 0; i < 2; i++) {
            const int ch = ac0 + i;
            const unsigned ad = (unsigned)(arow * 80 + ch * 16);
            cp16(base + 0 * H2TILE_A + ad, Ah + ao + ch * 8);                   // Ah
            cp16(base + (H2TILE_A + H2TILE_N) + ad, Al + ao + ch * 8);          // Al
        }
        cp16(base + H2TILE_A + bd, Bh + bo);                                    // Bh
        cp16(base + (2 * H2TILE_A + H2TILE_N) + bd, Bl + bo);                   // Bl
    };

    float acc[2][4][4];
#pragma unroll
    for (int i = 0; i < 2; i++)
#pragma unroll
        for (int j = 0; j < 4; j++)
#pragma unroll
            for (int r = 0; r < 4; r++) acc[i][j][r] = 0.f;

    const int r8 = lane & 7;
    const int hb = (lane >> 3) & 1;
    const int hf = lane >> 4;
    unsigned aOff[2], bOff[2];
#pragma unroll
    for (int mi = 0; mi < 2; mi++)
        aOff[mi] = ((wm + mi * 16 + r8 + hb * 8) * 40 + hf * 8) * 2;
#pragma unroll
    for (int p = 0; p < 2; p++)
        bOff[p] = ((wn + p * 16 + r8 + hf * 8) * 40) * 2 + hb * 16;

    const int niter = K >> 5;

    stageCopy(0, 0);
    asm volatile("cp.async.commit_group;");

    for (int it = 0; it < niter; it++) {
        if (it + 1 < niter) {
            stageCopy((it + 1) & 1, it + 1);
            asm volatile("cp.async.commit_group;");
            asm volatile("cp.async.wait_group 1;");
        } else {
            asm volatile("cp.async.wait_group 0;");
        }
        __syncthreads();

        const unsigned stB = smemU + (unsigned)((it & 1) * H2STAGE_B);
        const unsigned aH = stB;
        const unsigned bH = stB + H2TILE_A;
        const unsigned aL = stB + (H2TILE_A + H2TILE_N);
        const unsigned bL = stB + (2 * H2TILE_A + H2TILE_N);

#pragma unroll
        for (int ks = 0; ks < 2; ks++) {
            unsigned aFh[2][4], aFl[2][4];
            unsigned bFh[4][2], bFl[4][2];
#pragma unroll
            for (int mi = 0; mi < 2; mi++) {
                asm volatile("ldmatrix.sync.aligned.m8n8.x4.shared.b16 {%0,%1,%2,%3}, [%4];"
                    : "=r"(aFh[mi][0]), "=r"(aFh[mi][1]), "=r"(aFh[mi][2]), "=r"(aFh[mi][3])
                    : "r"(aH + aOff[mi] + ks * 32));
                asm volatile("ldmatrix.sync.aligned.m8n8.x4.shared.b16 {%0,%1,%2,%3}, [%4];"
                    : "=r"(aFl[mi][0]), "=r"(aFl[mi][1]), "=r"(aFl[mi][2]), "=r"(aFl[mi][3])
                    : "r"(aL + aOff[mi] + ks * 32));
            }
#pragma unroll
            for (int p = 0; p < 2; p++) {
                unsigned q0, q1, q2, q3;
                asm volatile("ldmatrix.sync.aligned.m8n8.x4.shared.b16 {%0,%1,%2,%3}, [%4];"
                    : "=r"(q0), "=r"(q1), "=r"(q2), "=r"(q3)
                    : "r"(bH + bOff[p] + ks * 32));
                bFh[2 * p][0] = q0; bFh[2 * p][1] = q1;
                bFh[2 * p + 1][0] = q2; bFh[2 * p + 1][1] = q3;
                asm volatile("ldmatrix.sync.aligned.m8n8.x4.shared.b16 {%0,%1,%2,%3}, [%4];"
                    : "=r"(q0), "=r"(q1), "=r"(q2), "=r"(q3)
                    : "r"(bL + bOff[p] + ks * 32));
                bFl[2 * p][0] = q0; bFl[2 * p][1] = q1;
                bFl[2 * p + 1][0] = q2; bFl[2 * p + 1][1] = q3;
            }
#pragma unroll
            for (int mi = 0; mi < 2; mi++)
#pragma unroll
                for (int nj = 0; nj < 4; nj++) {
                    MMAH(aFh, bFl, mi, nj, nj);
                    MMAH(aFl, bFh, mi, nj, nj);
                    MMAH(aFh, bFh, mi, nj, nj);
                }
        }
        __syncthreads();
    }

    // epilogue
    const int g = lane >> 2;
    const int t = lane & 3;
#pragma unroll
    for (int nj = 0; nj < 4; nj++) {
        const int col = n0 + wn + nj * 8 + t * 2;
        float b0 = 0.f, b1 = 0.f;
        if (EPI != 0) { b0 = bias[col]; b1 = bias[col + 1]; }
#pragma unroll
        for (int mi = 0; mi < 2; mi++) {
            const int row = m0 + wm + mi * 16 + g;
            float c0 = acc[mi][nj][0] + b0;
            float c1 = acc[mi][nj][1] + b1;
            float c2 = acc[mi][nj][2] + b0;
            float c3 = acc[mi][nj][3] + b1;
            if (EPI == 0) {
                float* Cp = Cf + (long)bz * sC;
                *reinterpret_cast<float2*>(&Cp[(long)row * ldc + col]) = make_float2(c0, c1);
                *reinterpret_cast<float2*>(&Cp[(long)(row + 8) * ldc + col]) = make_float2(c2, c3);
            } else if (EPI == 1) {
                __half h0 = __float2half_rn(c0), h1 = __float2half_rn(c1);
                __half h2 = __float2half_rn(c2), h3 = __float2half_rn(c3);
                __half l0 = __float2half_rn(c0 - __half2float(h0));
                __half l1 = __float2half_rn(c1 - __half2float(h1));
                __half l2 = __float2half_rn(c2 - __half2float(h2));
                __half l3 = __float2half_rn(c3 - __half2float(h3));
                *reinterpret_cast<unsigned*>(&Ch[(long)row * ldc + col])       = packh(h0, h1);
                *reinterpret_cast<unsigned*>(&Cl[(long)row * ldc + col])       = packh(l0, l1);
                *reinterpret_cast<unsigned*>(&Ch[(long)(row + 8) * ldc + col]) = packh(h2, h3);
                *reinterpret_cast<unsigned*>(&Cl[(long)(row + 8) * ldc + col]) = packh(l2, l3);
            } else {
                const int bb = row >> 12;
                const int s  = row & 4095;
                __half* Cp = Ch + (long)bb * EMB * SEQ + s;
                Cp[(long)col * SEQ]           = __float2half_rn(c0);
                Cp[(long)(col + 1) * SEQ]     = __float2half_rn(c1);
                Cp[(long)col * SEQ + 8]       = __float2half_rn(c2);
                Cp[(long)(col + 1) * SEQ + 8] = __float2half_rn(c3);
            }
        }
    }
}

// ===========================================================================
// AV GEMM x1 (single fp16 in, fp32 out) — validated round-11 kernel,
// unchanged (411 TF/s measured, 2 CTAs/SM).
// ===========================================================================
#define GTILE_B  18432
#define H1STAGE_B (2 * GTILE_B)
#define H1SMEM    (2 * H1STAGE_B)            // 73728 B

__global__ void __launch_bounds__(512)
gemm_h1_nt(const __half* __restrict__ A, const __half* __restrict__ B,
           float* __restrict__ C, int K, int lda, int ldb, int ldc,
           long sA, long sB, long sC)
{
    extern __shared__ unsigned su[];

    const int bz = blockIdx.z;
    A += (long)bz * sA;
    B += (long)bz * sB;
    C += (long)bz * sC;

    const int tid  = threadIdx.x;
    const int lane = tid & 31;
    const int wid  = tid >> 5;
    const int wm   = (wid & 3) * 32;
    const int wn   = (wid >> 2) * 32;
    const int m0   = blockIdx.y * 128;
    const int n0   = blockIdx.x * 128;

    unsigned smemU;
    asm("{ .reg .u64 t; cvta.to.shared.u64 t, %1; cvt.u32.u64 %0, t; }"
        : "=r"(smemU) : "l"(su));

    const int crow = tid >> 2;
    const int cc   = (tid & 3) * 8;
    const unsigned dsto = (unsigned)(crow * 144 + cc * 2);

    auto stageCopy = [&](int buf, int kt) {
        const unsigned base = smemU + (unsigned)buf * H1STAGE_B;
        const long ao = (long)(m0 + crow) * lda + (long)kt * 64 + cc;
        const long bo = (long)(n0 + crow) * ldb + (long)kt * 64 + cc;
        cp16(base + 0 * GTILE_B + dsto,      A + ao);
        cp16(base + 0 * GTILE_B + dsto + 64, A + ao + 32);
        cp16(base + 1 * GTILE_B + dsto,      B + bo);
        cp16(base + 1 * GTILE_B + dsto + 64, B + bo + 32);
    };

    float acc[2][4][4];
#pragma unroll
    for (int i = 0; i < 2; i++)
#pragma unroll
        for (int j = 0; j < 4; j++)
#pragma unroll
            for (int r = 0; r < 4; r++) acc[i][j][r] = 0.f;

    const int r8 = lane & 7;
    const int hb = (lane >> 3) & 1;
    const int hf = lane >> 4;
    unsigned aOff[2], bOff[2];
#pragma unroll
    for (int mi = 0; mi < 2; mi++)
        aOff[mi] = ((wm + mi * 16 + r8 + hb * 8) * 72 + hf * 8) * 2;
#pragma unroll
    for (int p = 0; p < 2; p++)
        bOff[p] = ((wn + p * 16 + r8 + hf * 8) * 72) * 2 + hb * 16;

    const int niter = K >> 6;

    stageCopy(0, 0);
    asm volatile("cp.async.commit_group;");

    for (int it = 0; it < niter; it++) {
        if (it + 1 < niter) {
            stageCopy((it + 1) & 1, it + 1);
            asm volatile("cp.async.commit_group;");
            asm volatile("cp.async.wait_group 1;");
        } else {
            asm volatile("cp.async.wait_group 0;");
        }
        __syncthreads();

        const unsigned stB = smemU + (unsigned)((it & 1) * H1STAGE_B);
        const unsigned aH = stB;
        const unsigned bH = stB + GTILE_B;

#pragma unroll
        for (int ks = 0; ks < 4; ks++) {
            unsigned aF[2][4];
            unsigned bF[4][2];
#pragma unroll
            for (int mi = 0; mi < 2; mi++) {
                asm volatile("ldmatrix.sync.aligned.m8n8.x4.shared.b16 {%0,%1,%2,%3}, [%4];"
                    : "=r"(aF[mi][0]), "=r"(aF[mi][1]), "=r"(aF[mi][2]), "=r"(aF[mi][3])
                    : "r"(aH + aOff[mi] + ks * 32));
            }
#pragma unroll
            for (int p = 0; p < 2; p++) {
                unsigned q0, q1, q2, q3;
                asm volatile("ldmatrix.sync.aligned.m8n8.x4.shared.b16 {%0,%1,%2,%3}, [%4];"
                    : "=r"(q0), "=r"(q1), "=r"(q2), "=r"(q3)
                    : "r"(bH + bOff[p] + ks * 32));
                bF[2 * p][0] = q0; bF[2 * p][1] = q1;
                bF[2 * p + 1][0] = q2; bF[2 * p + 1][1] = q3;
            }
#pragma unroll
            for (int mi = 0; mi < 2; mi++)
#pragma unroll
                for (int nj = 0; nj < 4; nj++)
                    MMAH(aF, bF, mi, nj, nj);
        }
        __syncthreads();
    }

    const int g = lane >> 2;
    const int t = lane & 3;
#pragma unroll
    for (int nj = 0; nj < 4; nj++) {
        const int col = n0 + wn + nj * 8 + t * 2;
#pragma unroll
        for (int mi = 0; mi < 2; mi++) {
            const int row = m0 + wm + mi * 16 + g;
            *reinterpret_cast<float2*>(&C[(long)row * ldc + col]) =
                make_float2(acc[mi][nj][0], acc[mi][nj][1]);
            *reinterpret_cast<float2*>(&C[(long)(row + 8) * ldc + col]) =
                make_float2(acc[mi][nj][2], acc[mi][nj][3]);
        }
    }
}

// ---------------------------------------------------------------------------
// Row softmax: fp32 scores -> single fp16 attn. 256 thr / 4096 cols.
// ---------------------------------------------------------------------------
__global__ void __launch_bounds__(256)
softmax_h(const float* __restrict__ S, __half* __restrict__ P)
{
    const long row = blockIdx.x;
    const float* p = S + row * (long)SEQ;
    const int tid  = threadIdx.x;
    const int lane = tid & 31;
    const int wid  = tid >> 5;

    float vals[16];
    float m = -3.0e38f;
#pragma unroll
    for (int i = 0; i < 4; i++) {
        float4 v = reinterpret_cast<const float4*>(p)[tid + i * 256];
        vals[i * 4 + 0] = v.x; vals[i * 4 + 1] = v.y;
        vals[i * 4 + 2] = v.z; vals[i * 4 + 3] = v.w;
        m = fmaxf(m, fmaxf(fmaxf(v.x, v.y), fmaxf(v.z, v.w)));
    }

    __shared__ float red[8];
#pragma unroll
    for (int off = 16; off > 0; off >>= 1)
        m = fmaxf(m, __shfl_xor_sync(0xffffffffu, m, off));
    if (lane == 0) red[wid] = m;
    __syncthreads();
    float mAll = red[0];
#pragma unroll
    for (int w = 1; w < 8; w++) mAll = fmaxf(mAll, red[w]);
    __syncthreads();

    float s = 0.f;
#pragma unroll
    for (int i = 0; i < 16; i++) {
        vals[i] = __expf(vals[i] - mAll);
        s += vals[i];
    }
#pragma unroll
    for (int off = 16; off > 0; off >>= 1)
        s += __shfl_xor_sync(0xffffffffu, s, off);
    if (lane == 0) red[wid] = s;
    __syncthreads();
    float sAll = 0.f;
#pragma unroll
    for (int w = 0; w < 8; w++) sAll += red[w];
    const float inv = 1.0f / sAll;

    uint2* ph = reinterpret_cast<uint2*>(P + row * (long)SEQ);
#pragma unroll
    for (int i = 0; i < 4; i++) {
        unsigned h0 = packh(__float2half_rn(vals[i * 4 + 0] * inv),
                            __float2half_rn(vals[i * 4 + 1] * inv));
        unsigned h1 = packh(__float2half_rn(vals[i * 4 + 2] * inv),
                            __float2half_rn(vals[i * 4 + 3] * inv));
        ph[tid + i * 256] = make_uint2(h0, h1);
    }
}

// ---------------------------------------------------------------------------
extern "C" void kernel_launch(void* const* d_in, const int* in_sizes, int n_in,
                              void* d_out, int out_size)
{
    const float* q_in = (const float*)d_in[0];
    const float* k_in = (const float*)d_in[1];
    const float* v_in = (const float*)d_in[2];
    const float* Wq   = (const float*)d_in[3];
    const float* bq   = (const float*)d_in[4];
    const float* Wk   = (const float*)d_in[5];
    const float* bk   = (const float*)d_in[6];
    const float* Wv   = (const float*)d_in[7];
    const float* bv   = (const float*)d_in[8];
    float* out = (float*)d_out;

    float* gs;
    __half *xqh, *xql, *xkh, *xkl, *xvh, *xvl;
    __half *wqh, *wql, *wkh, *wkl, *wvh, *wvl;
    __half *qh, *ql, *kh, *kl, *vt, *pp;
    cudaGetSymbolAddress((void**)&gs, g_s);
    cudaGetSymbolAddress((void**)&xqh, g_xqh); cudaGetSymbolAddress((void**)&xql, g_xql);
    cudaGetSymbolAddress((void**)&xkh, g_xkh); cudaGetSymbolAddress((void**)&xkl, g_xkl);
    cudaGetSymbolAddress((void**)&xvh, g_xvh); cudaGetSymbolAddress((void**)&xvl, g_xvl);
    cudaGetSymbolAddress((void**)&wqh, g_wqh); cudaGetSymbolAddress((void**)&wql, g_wql);
    cudaGetSymbolAddress((void**)&wkh, g_wkh); cudaGetSymbolAddress((void**)&wkl, g_wkl);
    cudaGetSymbolAddress((void**)&wvh, g_wvh); cudaGetSymbolAddress((void**)&wvl, g_wvl);
    cudaGetSymbolAddress((void**)&qh, g_qh);   cudaGetSymbolAddress((void**)&ql, g_ql);
    cudaGetSymbolAddress((void**)&kh, g_kh);   cudaGetSymbolAddress((void**)&kl, g_kl);
    cudaGetSymbolAddress((void**)&vt, g_vt);   cudaGetSymbolAddress((void**)&pp, g_p);

    static bool attrDone = false;
    if (!attrDone) {
        cudaFuncSetAttribute(gemm_h2<0>, cudaFuncAttributeMaxDynamicSharedMemorySize, H2SMEM);
        cudaFuncSetAttribute(gemm_h2<1>, cudaFuncAttributeMaxDynamicSharedMemorySize, H2SMEM);
        cudaFuncSetAttribute(gemm_h2<2>, cudaFuncAttributeMaxDynamicSharedMemorySize, H2SMEM);
        cudaFuncSetAttribute(gemm_h1_nt, cudaFuncAttributeMaxDynamicSharedMemorySize, H1SMEM);
        attrDone = true;
    }

    const int NX4 = BATCH * SEQ * EMB / 4;   // 2M float4
    const int NW4 = EMB * EMB / 4;           // 64K float4

    // 0) pre-split inputs & weights to fp16 h/l
    split_f32<<<2048, 256>>>(q_in, xqh, xql, NX4);
    split_f32<<<2048, 256>>>(k_in, xkh, xkl, NX4);
    split_f32<<<2048, 256>>>(v_in, xvh, xvl, NX4);
    split_f32<<<256, 256>>>(Wq, wqh, wql, NW4);
    split_f32<<<256, 256>>>(Wk, wkh, wkl, NW4);
    split_f32<<<256, 256>>>(Wv, wvh, wvl, NW4);

    // 1) projections (h2, CTA 128x64): Q,K split-out; V transposed single-out
    {
        dim3 grd(EMB / 64, (BATCH * SEQ) / 128, 1);
        gemm_h2<1><<<grd, 256, H2SMEM>>>(xqh, xql, wqh, wql, bq,
                                         nullptr, qh, ql, EMB, EMB, EMB, EMB, 0, 0, 0);
        gemm_h2<1><<<grd, 256, H2SMEM>>>(xkh, xkl, wkh, wkl, bk,
                                         nullptr, kh, kl, EMB, EMB, EMB, EMB, 0, 0, 0);
        gemm_h2<2><<<grd, 256, H2SMEM>>>(xvh, xvl, wvh, wvl, bv,
                                         nullptr, vt, nullptr, EMB, EMB, EMB, SEQ, 0, 0, 0);
    }

    // 2) scores[b] = q[b] @ k[b]^T  (h2, fp32 out, CTA 128x64)
    {
        dim3 grd(SEQ / 64, SEQ / 128, BATCH);
        gemm_h2<0><<<grd, 256, H2SMEM>>>(qh, ql, kh, kl, nullptr,
                                         gs, nullptr, nullptr, EMB, EMB, EMB, SEQ,
                                         (long)SEQ * EMB, (long)SEQ * EMB,
                                         (long)SEQ * SEQ);
    }

    // 3) softmax -> single fp16 attn
    softmax_h<<<BATCH * SEQ, 256>>>(gs, pp);

    // 4) out[b] = attn[b] @ v[b]  (h1)
    {
        dim3 grd(EMB / 128, SEQ / 128, BATCH);
        gemm_h1_nt<<<grd, 512, H1SMEM>>>(pp, vt, out, SEQ, SEQ, SEQ, EMB,
                                         (long)SEQ * SEQ, (long)EMB * SEQ,
                                         (long)SEQ * EMB);
    }
}

// round 15
// speedup vs baseline: 1.0779x; 1.0779x over previous
#include <cuda_runtime.h>
#include <cuda_fp16.h>
#include <math.h>

#define BATCH 4
#define SEQ   4096
#define EMB   512

// Scratch (__device__ globals: sanctioned, no runtime allocation)
__device__ float g_s[(size_t)BATCH * SEQ * SEQ];                  // 256 MB scores
__device__ __half g_xqh[BATCH * SEQ * EMB], g_xql[BATCH * SEQ * EMB];
__device__ __half g_xkh[BATCH * SEQ * EMB], g_xkl[BATCH * SEQ * EMB];
__device__ __half g_xvh[BATCH * SEQ * EMB], g_xvl[BATCH * SEQ * EMB];
__device__ __half g_wqh[EMB * EMB], g_wql[EMB * EMB];
__device__ __half g_wkh[EMB * EMB], g_wkl[EMB * EMB];
__device__ __half g_wvh[EMB * EMB], g_wvl[EMB * EMB];
__device__ __half g_qh[BATCH * SEQ * EMB], g_ql[BATCH * SEQ * EMB];
__device__ __half g_kh[BATCH * SEQ * EMB], g_kl[BATCH * SEQ * EMB];
__device__ __half g_vt[BATCH * SEQ * EMB];                        // [b][e][s]
__device__ __half g_p [(size_t)BATCH * SEQ * SEQ];                // 128 MB attn

__device__ __forceinline__ unsigned packh(__half a, __half b) {
    return ((unsigned)__half_as_ushort(b) << 16) | __half_as_ushort(a);
}
__device__ __forceinline__ void cp16(unsigned dst, const void* src) {
    asm volatile("cp.async.cg.shared.global [%0], [%1], 16;" :: "r"(dst), "l"(src));
}

#define MMAH(aa, bb, mi, aj, bj)                                              \
    asm volatile(                                                             \
        "mma.sync.aligned.m16n8k16.row.col.f32.f16.f16.f32 "                  \
        "{%0,%1,%2,%3}, {%4,%5,%6,%7}, {%8,%9}, {%0,%1,%2,%3};"               \
        : "+f"(acc[mi][aj][0]), "+f"(acc[mi][aj][1]),                         \
          "+f"(acc[mi][aj][2]), "+f"(acc[mi][aj][3])                          \
        : "r"(aa[mi][0]), "r"(aa[mi][1]), "r"(aa[mi][2]), "r"(aa[mi][3]),     \
          "r"(bb[bj][0]), "r"(bb[bj][1]))

// ---------------------------------------------------------------------------
// Elementwise fp32 -> split fp16 (h = rn(x), l = rn(x - h)), float4-wide.
// ---------------------------------------------------------------------------
__global__ void __launch_bounds__(256)
split_f32(const float* __restrict__ src, __half* __restrict__ H,
          __half* __restrict__ L, int n4)
{
    const int stride = gridDim.x * blockDim.x;
    for (int i = blockIdx.x * blockDim.x + threadIdx.x; i < n4; i += stride) {
        float4 v = reinterpret_cast<const float4*>(src)[i];
        __half h0 = __float2half_rn(v.x), h1 = __float2half_rn(v.y);
        __half h2 = __float2half_rn(v.z), h3 = __float2half_rn(v.w);
        __half l0 = __float2half_rn(v.x - __half2float(h0));
        __half l1 = __float2half_rn(v.y - __half2float(h1));
        __half l2 = __float2half_rn(v.z - __half2float(h2));
        __half l3 = __float2half_rn(v.w - __half2float(h3));
        reinterpret_cast<uint2*>(H)[i] = make_uint2(packh(h0, h1), packh(h2, h3));
        reinterpret_cast<uint2*>(L)[i] = make_uint2(packh(l0, l1), packh(l2, l3));
    }
}

// ===========================================================================
// h2 GEMM core (validated round-13 config): CTA 128x128, BK=32, 512 threads
// (16 warps 4m x 4n), warp tile 32x32, cp.async double buffer, rows padded
// to 40 fp16. EPI: 0 = fp32 C (score), 1 = split fp16 + bias (Q/K proj),
// 2 = transposed single fp16 + bias (V proj).
// ===========================================================================
#define H2TILE_B  10240                      // 128 * 40 * 2 bytes
#define H2STAGE_B (4 * H2TILE_B)             // 40960
#define H2SMEM    (2 * H2STAGE_B)            // 81920 B

template <int EPI>
__global__ void __launch_bounds__(512, 2)
gemm_h2(const __half* __restrict__ Ah, const __half* __restrict__ Al,
        const __half* __restrict__ Bh, const __half* __restrict__ Bl,
        const float* __restrict__ bias,
        float* __restrict__ Cf, __half* __restrict__ Ch, __half* __restrict__ Cl,
        int K, int lda, int ldb, int ldc,
        long sA, long sB, long sC)
{
    extern __shared__ unsigned su[];

    const int bz = blockIdx.z;
    Ah += (long)bz * sA; Al += (long)bz * sA;
    Bh += (long)bz * sB; Bl += (long)bz * sB;

    const int tid  = threadIdx.x;
    const int lane = tid & 31;
    const int wid  = tid >> 5;
    const int wm   = (wid & 3) * 32;
    const int wn   = (wid >> 2) * 32;
    const int m0   = blockIdx.y * 128;
    const int n0   = blockIdx.x * 128;

    unsigned smemU;
    asm("{ .reg .u64 t; cvta.to.shared.u64 t, %1; cvt.u32.u64 %0, t; }"
        : "=r"(smemU) : "l"(su));

    const int crow = tid >> 2;               // 0..127
    const int cch  = tid & 3;                // chunk 0..3
    const unsigned dsto = (unsigned)(crow * 80 + cch * 16);

    auto stageCopy = [&](int buf, int kt) {
        const unsigned base = smemU + (unsigned)buf * H2STAGE_B;
        const long ao = (long)(m0 + crow) * lda + (long)kt * 32 + cch * 8;
        const long bo = (long)(n0 + crow) * ldb + (long)kt * 32 + cch * 8;
        cp16(base + 0 * H2TILE_B + dsto, Ah + ao);
        cp16(base + 1 * H2TILE_B + dsto, Bh + bo);
        cp16(base + 2 * H2TILE_B + dsto, Al + ao);
        cp16(base + 3 * H2TILE_B + dsto, Bl + bo);
    };

    float acc[2][4][4];
#pragma unroll
    for (int i = 0; i < 2; i++)
#pragma unroll
        for (int j = 0; j < 4; j++)
#pragma unroll
            for (int r = 0; r < 4; r++) acc[i][j][r] = 0.f;

    const int r8 = lane & 7;
    const int hb = (lane >> 3) & 1;
    const int hf = lane >> 4;
    unsigned aOff[2], bOff[2];
#pragma unroll
    for (int mi = 0; mi < 2; mi++)
        aOff[mi] = ((wm + mi * 16 + r8 + hb * 8) * 40 + hf * 8) * 2;
#pragma unroll
    for (int p = 0; p < 2; p++)
        bOff[p] = ((wn + p * 16 + r8 + hf * 8) * 40) * 2 + hb * 16;

    const int niter = K >> 5;

    stageCopy(0, 0);
    asm volatile("cp.async.commit_group;");

    for (int it = 0; it < niter; it++) {
        if (it + 1 < niter) {
            stageCopy((it + 1) & 1, it + 1);
            asm volatile("cp.async.commit_group;");
            asm volatile("cp.async.wait_group 1;");
        } else {
            asm volatile("cp.async.wait_group 0;");
        }
        __syncthreads();

        const unsigned stB = smemU + (unsigned)((it & 1) * H2STAGE_B);
        const unsigned aH = stB;
        const unsigned bH = stB + H2TILE_B;
        const unsigned aL = stB + 2u * H2TILE_B;
        const unsigned bL = stB + 3u * H2TILE_B;

#pragma unroll
        for (int ks = 0; ks < 2; ks++) {
            unsigned aFh[2][4], aFl[2][4];
            unsigned bFh[4][2], bFl[4][2];
#pragma unroll
            for (int mi = 0; mi < 2; mi++) {
                asm volatile("ldmatrix.sync.aligned.m8n8.x4.shared.b16 {%0,%1,%2,%3}, [%4];"
                    : "=r"(aFh[mi][0]), "=r"(aFh[mi][1]), "=r"(aFh[mi][2]), "=r"(aFh[mi][3])
                    : "r"(aH + aOff[mi] + ks * 32));
                asm volatile("ldmatrix.sync.aligned.m8n8.x4.shared.b16 {%0,%1,%2,%3}, [%4];"
                    : "=r"(aFl[mi][0]), "=r"(aFl[mi][1]), "=r"(aFl[mi][2]), "=r"(aFl[mi][3])
                    : "r"(aL + aOff[mi] + ks * 32));
            }
#pragma unroll
            for (int p = 0; p < 2; p++) {
                unsigned q0, q1, q2, q3;
                asm volatile("ldmatrix.sync.aligned.m8n8.x4.shared.b16 {%0,%1,%2,%3}, [%4];"
                    : "=r"(q0), "=r"(q1), "=r"(q2), "=r"(q3)
                    : "r"(bH + bOff[p] + ks * 32));
                bFh[2 * p][0] = q0; bFh[2 * p][1] = q1;
                bFh[2 * p + 1][0] = q2; bFh[2 * p + 1][1] = q3;
                asm volatile("ldmatrix.sync.aligned.m8n8.x4.shared.b16 {%0,%1,%2,%3}, [%4];"
                    : "=r"(q0), "=r"(q1), "=r"(q2), "=r"(q3)
                    : "r"(bL + bOff[p] + ks * 32));
                bFl[2 * p][0] = q0; bFl[2 * p][1] = q1;
                bFl[2 * p + 1][0] = q2; bFl[2 * p + 1][1] = q3;
            }
#pragma unroll
            for (int mi = 0; mi < 2; mi++)
#pragma unroll
                for (int nj = 0; nj < 4; nj++) {
                    MMAH(aFh, bFl, mi, nj, nj);
                    MMAH(aFl, bFh, mi, nj, nj);
                    MMAH(aFh, bFh, mi, nj, nj);
                }
        }
        __syncthreads();
    }

    // epilogue
    const int g = lane >> 2;
    const int t = lane & 3;
#pragma unroll
    for (int nj = 0; nj < 4; nj++) {
        const int col = n0 + wn + nj * 8 + t * 2;
        float b0 = 0.f, b1 = 0.f;
        if (EPI != 0) { b0 = bias[col]; b1 = bias[col + 1]; }
#pragma unroll
        for (int mi = 0; mi < 2; mi++) {
            const int row = m0 + wm + mi * 16 + g;
            float c0 = acc[mi][nj][0] + b0;
            float c1 = acc[mi][nj][1] + b1;
            float c2 = acc[mi][nj][2] + b0;
            float c3 = acc[mi][nj][3] + b1;
            if (EPI == 0) {
                float* Cp = Cf + (long)bz * sC;
                *reinterpret_cast<float2*>(&Cp[(long)row * ldc + col]) = make_float2(c0, c1);
                *reinterpret_cast<float2*>(&Cp[(long)(row + 8) * ldc + col]) = make_float2(c2, c3);
            } else if (EPI == 1) {
                __half h0 = __float2half_rn(c0), h1 = __float2half_rn(c1);
                __half h2 = __float2half_rn(c2), h3 = __float2half_rn(c3);
                __half l0 = __float2half_rn(c0 - __half2float(h0));
                __half l1 = __float2half_rn(c1 - __half2float(h1));
                __half l2 = __float2half_rn(c2 - __half2float(h2));
                __half l3 = __float2half_rn(c3 - __half2float(h3));
                *reinterpret_cast<unsigned*>(&Ch[(long)row * ldc + col])       = packh(h0, h1);
                *reinterpret_cast<unsigned*>(&Cl[(long)row * ldc + col])       = packh(l0, l1);
                *reinterpret_cast<unsigned*>(&Ch[(long)(row + 8) * ldc + col]) = packh(h2, h3);
                *reinterpret_cast<unsigned*>(&Cl[(long)(row + 8) * ldc + col]) = packh(l2, l3);
            } else {
                const int bb = row >> 12;
                const int s  = row & 4095;
                __half* Cp = Ch + (long)bb * EMB * SEQ + s;
                Cp[(long)col * SEQ]           = __float2half_rn(c0);
                Cp[(long)(col + 1) * SEQ]     = __float2half_rn(c1);
                Cp[(long)col * SEQ + 8]       = __float2half_rn(c2);
                Cp[(long)(col + 1) * SEQ + 8] = __float2half_rn(c3);
            }
        }
    }
}

// ===========================================================================
// AV GEMM x1 (single fp16 in, fp32 out) — validated kernel, 2 CTAs/SM.
// ===========================================================================
#define GTILE_B  18432
#define H1STAGE_B (2 * GTILE_B)
#define H1SMEM    (2 * H1STAGE_B)            // 73728 B

__global__ void __launch_bounds__(512)
gemm_h1_nt(const __half* __restrict__ A, const __half* __restrict__ B,
           float* __restrict__ C, int K, int lda, int ldb, int ldc,
           long sA, long sB, long sC)
{
    extern __shared__ unsigned su[];

    const int bz = blockIdx.z;
    A += (long)bz * sA;
    B += (long)bz * sB;
    C += (long)bz * sC;

    const int tid  = threadIdx.x;
    const int lane = tid & 31;
    const int wid  = tid >> 5;
    const int wm   = (wid & 3) * 32;
    const int wn   = (wid >> 2) * 32;
    const int m0   = blockIdx.y * 128;
    const int n0   = blockIdx.x * 128;

    unsigned smemU;
    asm("{ .reg .u64 t; cvta.to.shared.u64 t, %1; cvt.u32.u64 %0, t; }"
        : "=r"(smemU) : "l"(su));

    const int crow = tid >> 2;
    const int cc   = (tid & 3) * 8;
    const unsigned dsto = (unsigned)(crow * 144 + cc * 2);

    auto stageCopy = [&](int buf, int kt) {
        const unsigned base = smemU + (unsigned)buf * H1STAGE_B;
        const long ao = (long)(m0 + crow) * lda + (long)kt * 64 + cc;
        const long bo = (long)(n0 + crow) * ldb + (long)kt * 64 + cc;
        cp16(base + 0 * GTILE_B + dsto,      A + ao);
        cp16(base + 0 * GTILE_B + dsto + 64, A + ao + 32);
        cp16(base + 1 * GTILE_B + dsto,      B + bo);
        cp16(base + 1 * GTILE_B + dsto + 64, B + bo + 32);
    };

    float acc[2][4][4];
#pragma unroll
    for (int i = 0; i < 2; i++)
#pragma unroll
        for (int j = 0; j < 4; j++)
#pragma unroll
            for (int r = 0; r < 4; r++) acc[i][j][r] = 0.f;

    const int r8 = lane & 7;
    const int hb = (lane >> 3) & 1;
    const int hf = lane >> 4;
    unsigned aOff[2], bOff[2];
#pragma unroll
    for (int mi = 0; mi < 2; mi++)
        aOff[mi] = ((wm + mi * 16 + r8 + hb * 8) * 72 + hf * 8) * 2;
#pragma unroll
    for (int p = 0; p < 2; p++)
        bOff[p] = ((wn + p * 16 + r8 + hf * 8) * 72) * 2 + hb * 16;

    const int niter = K >> 6;

    stageCopy(0, 0);
    asm volatile("cp.async.commit_group;");

    for (int it = 0; it < niter; it++) {
        if (it + 1 < niter) {
            stageCopy((it + 1) & 1, it + 1);
            asm volatile("cp.async.commit_group;");
            asm volatile("cp.async.wait_group 1;");
        } else {
            asm volatile("cp.async.wait_group 0;");
        }
        __syncthreads();

        const unsigned stB = smemU + (unsigned)((it & 1) * H1STAGE_B);
        const unsigned aH = stB;
        const unsigned bH = stB + GTILE_B;

#pragma unroll
        for (int ks = 0; ks < 4; ks++) {
            unsigned aF[2][4];
            unsigned bF[4][2];
#pragma unroll
            for (int mi = 0; mi < 2; mi++) {
                asm volatile("ldmatrix.sync.aligned.m8n8.x4.shared.b16 {%0,%1,%2,%3}, [%4];"
                    : "=r"(aF[mi][0]), "=r"(aF[mi][1]), "=r"(aF[mi][2]), "=r"(aF[mi][3])
                    : "r"(aH + aOff[mi] + ks * 32));
            }
#pragma unroll
            for (int p = 0; p < 2; p++) {
                unsigned q0, q1, q2, q3;
                asm volatile("ldmatrix.sync.aligned.m8n8.x4.shared.b16 {%0,%1,%2,%3}, [%4];"
                    : "=r"(q0), "=r"(q1), "=r"(q2), "=r"(q3)
                    : "r"(bH + bOff[p] + ks * 32));
                bF[2 * p][0] = q0; bF[2 * p][1] = q1;
                bF[2 * p + 1][0] = q2; bF[2 * p + 1][1] = q3;
            }
#pragma unroll
            for (int mi = 0; mi < 2; mi++)
#pragma unroll
                for (int nj = 0; nj < 4; nj++)
                    MMAH(aF, bF, mi, nj, nj);
        }
        __syncthreads();
    }

    const int g = lane >> 2;
    const int t = lane & 3;
#pragma unroll
    for (int nj = 0; nj < 4; nj++) {
        const int col = n0 + wn + nj * 8 + t * 2;
#pragma unroll
        for (int mi = 0; mi < 2; mi++) {
            const int row = m0 + wm + mi * 16 + g;
            *reinterpret_cast<float2*>(&C[(long)row * ldc + col]) =
                make_float2(acc[mi][nj][0], acc[mi][nj][1]);
            *reinterpret_cast<float2*>(&C[(long)(row + 8) * ldc + col]) =
                make_float2(acc[mi][nj][2], acc[mi][nj][3]);
        }
    }
}

// ---------------------------------------------------------------------------
// Row softmax: fp32 scores -> single fp16 attn. 256 thr / 4096 cols.
// ---------------------------------------------------------------------------
__global__ void __launch_bounds__(256)
softmax_h(const float* __restrict__ S, __half* __restrict__ P)
{
    const long row = blockIdx.x;
    const float* p = S + row * (long)SEQ;
    const int tid  = threadIdx.x;
    const int lane = tid & 31;
    const int wid  = tid >> 5;

    float vals[16];
    float m = -3.0e38f;
#pragma unroll
    for (int i = 0; i < 4; i++) {
        float4 v = reinterpret_cast<const float4*>(p)[tid + i * 256];
        vals[i * 4 + 0] = v.x; vals[i * 4 + 1] = v.y;
        vals[i * 4 + 2] = v.z; vals[i * 4 + 3] = v.w;
        m = fmaxf(m, fmaxf(fmaxf(v.x, v.y), fmaxf(v.z, v.w)));
    }

    __shared__ float red[8];
#pragma unroll
    for (int off = 16; off > 0; off >>= 1)
        m = fmaxf(m, __shfl_xor_sync(0xffffffffu, m, off));
    if (lane == 0) red[wid] = m;
    __syncthreads();
    float mAll = red[0];
#pragma unroll
    for (int w = 1; w < 8; w++) mAll = fmaxf(mAll, red[w]);
    __syncthreads();

    float s = 0.f;
#pragma unroll
    for (int i = 0; i < 16; i++) {
        vals[i] = __expf(vals[i] - mAll);
        s += vals[i];
    }
#pragma unroll
    for (int off = 16; off > 0; off >>= 1)
        s += __shfl_xor_sync(0xffffffffu, s, off);
    if (lane == 0) red[wid] = s;
    __syncthreads();
    float sAll = 0.f;
#pragma unroll
    for (int w = 0; w < 8; w++) sAll += red[w];
    const float inv = 1.0f / sAll;

    uint2* ph = reinterpret_cast<uint2*>(P + row * (long)SEQ);
#pragma unroll
    for (int i = 0; i < 4; i++) {
        unsigned h0 = packh(__float2half_rn(vals[i * 4 + 0] * inv),
                            __float2half_rn(vals[i * 4 + 1] * inv));
        unsigned h1 = packh(__float2half_rn(vals[i * 4 + 2] * inv),
                            __float2half_rn(vals[i * 4 + 3] * inv));
        ph[tid + i * 256] = make_uint2(h0, h1);
    }
}

// ---------------------------------------------------------------------------
extern "C" void kernel_launch(void* const* d_in, const int* in_sizes, int n_in,
                              void* d_out, int out_size)
{
    const float* q_in = (const float*)d_in[0];
    const float* k_in = (const float*)d_in[1];
    const float* v_in = (const float*)d_in[2];
    const float* Wq   = (const float*)d_in[3];
    const float* bq   = (const float*)d_in[4];
    const float* Wk   = (const float*)d_in[5];
    const float* bk   = (const float*)d_in[6];
    const float* Wv   = (const float*)d_in[7];
    const float* bv   = (const float*)d_in[8];
    float* out = (float*)d_out;

    float* gs;
    __half *xqh, *xql, *xkh, *xkl, *xvh, *xvl;
    __half *wqh, *wql, *wkh, *wkl, *wvh, *wvl;
    __half *qh, *ql, *kh, *kl, *vt, *pp;
    cudaGetSymbolAddress((void**)&gs, g_s);
    cudaGetSymbolAddress((void**)&xqh, g_xqh); cudaGetSymbolAddress((void**)&xql, g_xql);
    cudaGetSymbolAddress((void**)&xkh, g_xkh); cudaGetSymbolAddress((void**)&xkl, g_xkl);
    cudaGetSymbolAddress((void**)&xvh, g_xvh); cudaGetSymbolAddress((void**)&xvl, g_xvl);
    cudaGetSymbolAddress((void**)&wqh, g_wqh); cudaGetSymbolAddress((void**)&wql, g_wql);
    cudaGetSymbolAddress((void**)&wkh, g_wkh); cudaGetSymbolAddress((void**)&wkl, g_wkl);
    cudaGetSymbolAddress((void**)&wvh, g_wvh); cudaGetSymbolAddress((void**)&wvl, g_wvl);
    cudaGetSymbolAddress((void**)&qh, g_qh);   cudaGetSymbolAddress((void**)&ql, g_ql);
    cudaGetSymbolAddress((void**)&kh, g_kh);   cudaGetSymbolAddress((void**)&kl, g_kl);
    cudaGetSymbolAddress((void**)&vt, g_vt);   cudaGetSymbolAddress((void**)&pp, g_p);

    static cudaStream_t sSide = nullptr;
    static cudaEvent_t evFork = nullptr, evV = nullptr;
    static bool attrDone = false;
    if (!attrDone) {
        cudaFuncSetAttribute(gemm_h2<0>, cudaFuncAttributeMaxDynamicSharedMemorySize, H2SMEM);
        cudaFuncSetAttribute(gemm_h2<1>, cudaFuncAttributeMaxDynamicSharedMemorySize, H2SMEM);
        cudaFuncSetAttribute(gemm_h2<2>, cudaFuncAttributeMaxDynamicSharedMemorySize, H2SMEM);
        cudaFuncSetAttribute(gemm_h1_nt, cudaFuncAttributeMaxDynamicSharedMemorySize, H1SMEM);
        cudaStreamCreateWithFlags(&sSide, cudaStreamNonBlocking);
        cudaEventCreateWithFlags(&evFork, cudaEventDisableTiming);
        cudaEventCreateWithFlags(&evV, cudaEventDisableTiming);
        attrDone = true;
    }

    const int NX4 = BATCH * SEQ * EMB / 4;   // 2M float4
    const int NW4 = EMB * EMB / 4;           // 64K float4

    // fork: V-projection chain runs on side stream, overlapped with the
    // Q/K projections and the score GEMM (AV is the only consumer of vt).
    cudaEventRecord(evFork, 0);
    cudaStreamWaitEvent(sSide, evFork, 0);

    // side chain: splitV, splitWv, projV -> vt
    split_f32<<<2048, 256, 0, sSide>>>(v_in, xvh, xvl, NX4);
    split_f32<<<256, 256, 0, sSide>>>(Wv, wvh, wvl, NW4);
    {
        dim3 grd(EMB / 128, (BATCH * SEQ) / 128, 1);
        gemm_h2<2><<<grd, 512, H2SMEM, sSide>>>(xvh, xvl, wvh, wvl, bv,
                                                nullptr, vt, nullptr,
                                                EMB, EMB, EMB, SEQ, 0, 0, 0);
    }
    cudaEventRecord(evV, sSide);

    // main chain
    split_f32<<<2048, 256>>>(q_in, xqh, xql, NX4);
    split_f32<<<2048, 256>>>(k_in, xkh, xkl, NX4);
    split_f32<<<256, 256>>>(Wq, wqh, wql, NW4);
    split_f32<<<256, 256>>>(Wk, wkh, wkl, NW4);

    {
        dim3 grd(EMB / 128, (BATCH * SEQ) / 128, 1);
        gemm_h2<1><<<grd, 512, H2SMEM>>>(xqh, xql, wqh, wql, bq,
                                         nullptr, qh, ql, EMB, EMB, EMB, EMB, 0, 0, 0);
        gemm_h2<1><<<grd, 512, H2SMEM>>>(xkh, xkl, wkh, wkl, bk,
                                         nullptr, kh, kl, EMB, EMB, EMB, EMB, 0, 0, 0);
    }

    // scores[b] = q[b] @ k[b]^T  (h2, fp32 out)
    {
        dim3 grd(SEQ / 128, SEQ / 128, BATCH);
        gemm_h2<0><<<grd, 512, H2SMEM>>>(qh, ql, kh, kl, nullptr,
                                         gs, nullptr, nullptr, EMB, EMB, EMB, SEQ,
                                         (long)SEQ * EMB, (long)SEQ * EMB,
                                         (long)SEQ * SEQ);
    }

    // softmax -> single fp16 attn
    softmax_h<<<BATCH * SEQ, 256>>>(gs, pp);

    // join: AV needs vt from side stream
    cudaStreamWaitEvent(0, evV, 0);

    // out[b] = attn[b] @ v[b]  (h1)
    {
        dim3 grd(EMB / 128, SEQ / 128, BATCH);
        gemm_h1_nt<<<grd, 512, H1SMEM>>>(pp, vt, out, SEQ, SEQ, SEQ, EMB,
                                         (long)SEQ * SEQ, (long)EMB * SEQ,
                                         (long)SEQ * EMB);
    }
}

// round 16
// speedup vs baseline: 1.1532x; 1.0698x over previous
#include <cuda_runtime.h>
#include <cuda_fp16.h>
#include <math.h>

#define BATCH 4
#define SEQ   4096
#define EMB   512

// Scratch (__device__ globals: sanctioned, no runtime allocation)
__device__ float g_s[(size_t)BATCH * SEQ * SEQ];                  // 256 MB scores
__device__ __half g_xqh[BATCH * SEQ * EMB], g_xql[BATCH * SEQ * EMB];
__device__ __half g_xkh[BATCH * SEQ * EMB], g_xkl[BATCH * SEQ * EMB];
__device__ __half g_xvh[BATCH * SEQ * EMB], g_xvl[BATCH * SEQ * EMB];
__device__ __half g_wqh[EMB * EMB], g_wql[EMB * EMB];
__device__ __half g_wkh[EMB * EMB], g_wkl[EMB * EMB];
__device__ __half g_wvh[EMB * EMB], g_wvl[EMB * EMB];
__device__ __half g_qh[BATCH * SEQ * EMB], g_ql[BATCH * SEQ * EMB];
__device__ __half g_kh[BATCH * SEQ * EMB], g_kl[BATCH * SEQ * EMB];
__device__ __half g_vt[BATCH * SEQ * EMB];                        // [b][e][s]
__device__ __half g_p [(size_t)BATCH * SEQ * SEQ];                // 128 MB attn

__device__ __forceinline__ unsigned packh(__half a, __half b) {
    return ((unsigned)__half_as_ushort(b) << 16) | __half_as_ushort(a);
}
__device__ __forceinline__ void cp16(unsigned dst, const void* src) {
    asm volatile("cp.async.cg.shared.global [%0], [%1], 16;" :: "r"(dst), "l"(src));
}

#define MMAH(aa, bb, mi, aj, bj)                                              \
    asm volatile(                                                             \
        "mma.sync.aligned.m16n8k16.row.col.f32.f16.f16.f32 "                  \
        "{%0,%1,%2,%3}, {%4,%5,%6,%7}, {%8,%9}, {%0,%1,%2,%3};"               \
        : "+f"(acc[mi][aj][0]), "+f"(acc[mi][aj][1]),                         \
          "+f"(acc[mi][aj][2]), "+f"(acc[mi][aj][3])                          \
        : "r"(aa[mi][0]), "r"(aa[mi][1]), "r"(aa[mi][2]), "r"(aa[mi][3]),     \
          "r"(bb[bj][0]), "r"(bb[bj][1]))

// ---------------------------------------------------------------------------
// Elementwise fp32 -> split fp16 (h = rn(x), l = rn(x - h)), float4-wide.
// ---------------------------------------------------------------------------
__global__ void __launch_bounds__(256)
split_f32(const float* __restrict__ src, __half* __restrict__ H,
          __half* __restrict__ L, int n4)
{
    const int stride = gridDim.x * blockDim.x;
    for (int i = blockIdx.x * blockDim.x + threadIdx.x; i < n4; i += stride) {
        float4 v = reinterpret_cast<const float4*>(src)[i];
        __half h0 = __float2half_rn(v.x), h1 = __float2half_rn(v.y);
        __half h2 = __float2half_rn(v.z), h3 = __float2half_rn(v.w);
        __half l0 = __float2half_rn(v.x - __half2float(h0));
        __half l1 = __float2half_rn(v.y - __half2float(h1));
        __half l2 = __float2half_rn(v.z - __half2float(h2));
        __half l3 = __float2half_rn(v.w - __half2float(h3));
        reinterpret_cast<uint2*>(H)[i] = make_uint2(packh(h0, h1), packh(h2, h3));
        reinterpret_cast<uint2*>(L)[i] = make_uint2(packh(l0, l1), packh(l2, l3));
    }
}

// ===========================================================================
// h2 GEMM core: CTA 128x128, BK=32, 512 threads (16 warps 4m x 4n), warp
// tile 32x32, cp.async double buffer, rows padded to 40 fp16.
// REGISTER-LEAN pass ordering: only ONE A-frag set + ONE B-frag set live:
//   load aFh,bFl -> hl ; reload b<-bFh -> hh ; reload a<-aFl -> lh.
// 32 acc + 16 frag + addr ~= 60 regs -> __launch_bounds__(512,2) = 2 CTA/SM.
// EPI: 0 = fp32 C (score), 1 = split fp16 + bias (Q/K proj),
//      2 = transposed single fp16 + bias (V proj).
// ===========================================================================
#define H2TILE_B  10240                      // 128 * 40 * 2 bytes
#define H2STAGE_B (4 * H2TILE_B)             // 40960
#define H2SMEM    (2 * H2STAGE_B)            // 81920 B

template <int EPI>
__global__ void __launch_bounds__(512, 2)
gemm_h2(const __half* __restrict__ Ah, const __half* __restrict__ Al,
        const __half* __restrict__ Bh, const __half* __restrict__ Bl,
        const float* __restrict__ bias,
        float* __restrict__ Cf, __half* __restrict__ Ch, __half* __restrict__ Cl,
        int K, int lda, int ldb, int ldc,
        long sA, long sB, long sC)
{
    extern __shared__ unsigned su[];

    const int bz = blockIdx.z;
    Ah += (long)bz * sA; Al += (long)bz * sA;
    Bh += (long)bz * sB; Bl += (long)bz * sB;

    const int tid  = threadIdx.x;
    const int lane = tid & 31;
    const int wid  = tid >> 5;
    const int wm   = (wid & 3) * 32;
    const int wn   = (wid >> 2) * 32;
    const int m0   = blockIdx.y * 128;
    const int n0   = blockIdx.x * 128;

    unsigned smemU;
    asm("{ .reg .u64 t; cvta.to.shared.u64 t, %1; cvt.u32.u64 %0, t; }"
        : "=r"(smemU) : "l"(su));

    const int crow = tid >> 2;               // 0..127
    const int cch  = tid & 3;                // chunk 0..3
    const unsigned dsto = (unsigned)(crow * 80 + cch * 16);

    auto stageCopy = [&](int buf, int kt) {
        const unsigned base = smemU + (unsigned)buf * H2STAGE_B;
        const long ao = (long)(m0 + crow) * lda + (long)kt * 32 + cch * 8;
        const long bo = (long)(n0 + crow) * ldb + (long)kt * 32 + cch * 8;
        cp16(base + 0 * H2TILE_B + dsto, Ah + ao);
        cp16(base + 1 * H2TILE_B + dsto, Bh + bo);
        cp16(base + 2 * H2TILE_B + dsto, Al + ao);
        cp16(base + 3 * H2TILE_B + dsto, Bl + bo);
    };

    float acc[2][4][4];
#pragma unroll
    for (int i = 0; i < 2; i++)
#pragma unroll
        for (int j = 0; j < 4; j++)
#pragma unroll
            for (int r = 0; r < 4; r++) acc[i][j][r] = 0.f;

    const int r8 = lane & 7;
    const int hb = (lane >> 3) & 1;
    const int hf = lane >> 4;
    unsigned aOff[2], bOff[2];
#pragma unroll
    for (int mi = 0; mi < 2; mi++)
        aOff[mi] = ((wm + mi * 16 + r8 + hb * 8) * 40 + hf * 8) * 2;
#pragma unroll
    for (int p = 0; p < 2; p++)
        bOff[p] = ((wn + p * 16 + r8 + hf * 8) * 40) * 2 + hb * 16;

    const int niter = K >> 5;

    stageCopy(0, 0);
    asm volatile("cp.async.commit_group;");

    for (int it = 0; it < niter; it++) {
        if (it + 1 < niter) {
            stageCopy((it + 1) & 1, it + 1);
            asm volatile("cp.async.commit_group;");
            asm volatile("cp.async.wait_group 1;");
        } else {
            asm volatile("cp.async.wait_group 0;");
        }
        __syncthreads();

        const unsigned stB = smemU + (unsigned)((it & 1) * H2STAGE_B);
        const unsigned aH = stB;
        const unsigned bH = stB + H2TILE_B;
        const unsigned aL = stB + 2u * H2TILE_B;
        const unsigned bL = stB + 3u * H2TILE_B;

#pragma unroll
        for (int ks = 0; ks < 2; ks++) {
            unsigned aF[2][4];       // single live A-fragment set
            unsigned bF[4][2];       // single live B-fragment set

            // --- pass 1: aFh x bFl (hl) ---
#pragma unroll
            for (int mi = 0; mi < 2; mi++)
                asm volatile("ldmatrix.sync.aligned.m8n8.x4.shared.b16 {%0,%1,%2,%3}, [%4];"
                    : "=r"(aF[mi][0]), "=r"(aF[mi][1]), "=r"(aF[mi][2]), "=r"(aF[mi][3])
                    : "r"(aH + aOff[mi] + ks * 32));
#pragma unroll
            for (int p = 0; p < 2; p++) {
                unsigned q0, q1, q2, q3;
                asm volatile("ldmatrix.sync.aligned.m8n8.x4.shared.b16 {%0,%1,%2,%3}, [%4];"
                    : "=r"(q0), "=r"(q1), "=r"(q2), "=r"(q3)
                    : "r"(bL + bOff[p] + ks * 32));
                bF[2 * p][0] = q0; bF[2 * p][1] = q1;
                bF[2 * p + 1][0] = q2; bF[2 * p + 1][1] = q3;
            }
#pragma unroll
            for (int mi = 0; mi < 2; mi++)
#pragma unroll
                for (int nj = 0; nj < 4; nj++)
                    MMAH(aF, bF, mi, nj, nj);

            // --- pass 2: aFh x bFh (hh): reload B only ---
#pragma unroll
            for (int p = 0; p < 2; p++) {
                unsigned q0, q1, q2, q3;
                asm volatile("ldmatrix.sync.aligned.m8n8.x4.shared.b16 {%0,%1,%2,%3}, [%4];"
                    : "=r"(q0), "=r"(q1), "=r"(q2), "=r"(q3)
                    : "r"(bH + bOff[p] + ks * 32));
                bF[2 * p][0] = q0; bF[2 * p][1] = q1;
                bF[2 * p + 1][0] = q2; bF[2 * p + 1][1] = q3;
            }
#pragma unroll
            for (int mi = 0; mi < 2; mi++)
#pragma unroll
                for (int nj = 0; nj < 4; nj++)
                    MMAH(aF, bF, mi, nj, nj);

            // --- pass 3: aFl x bFh (lh): reload A only ---
#pragma unroll
            for (int mi = 0; mi < 2; mi++)
                asm volatile("ldmatrix.sync.aligned.m8n8.x4.shared.b16 {%0,%1,%2,%3}, [%4];"
                    : "=r"(aF[mi][0]), "=r"(aF[mi][1]), "=r"(aF[mi][2]), "=r"(aF[mi][3])
                    : "r"(aL + aOff[mi] + ks * 32));
#pragma unroll
            for (int mi = 0; mi < 2; mi++)
#pragma unroll
                for (int nj = 0; nj < 4; nj++)
                    MMAH(aF, bF, mi, nj, nj);
        }
        __syncthreads();
    }

    // epilogue
    const int g = lane >> 2;
    const int t = lane & 3;
#pragma unroll
    for (int nj = 0; nj < 4; nj++) {
        const int col = n0 + wn + nj * 8 + t * 2;
        float b0 = 0.f, b1 = 0.f;
        if (EPI != 0) { b0 = bias[col]; b1 = bias[col + 1]; }
#pragma unroll
        for (int mi = 0; mi < 2; mi++) {
            const int row = m0 + wm + mi * 16 + g;
            float c0 = acc[mi][nj][0] + b0;
            float c1 = acc[mi][nj][1] + b1;
            float c2 = acc[mi][nj][2] + b0;
            float c3 = acc[mi][nj][3] + b1;
            if (EPI == 0) {
                float* Cp = Cf + (long)bz * sC;
                *reinterpret_cast<float2*>(&Cp[(long)row * ldc + col]) = make_float2(c0, c1);
                *reinterpret_cast<float2*>(&Cp[(long)(row + 8) * ldc + col]) = make_float2(c2, c3);
            } else if (EPI == 1) {
                __half h0 = __float2half_rn(c0), h1 = __float2half_rn(c1);
                __half h2 = __float2half_rn(c2), h3 = __float2half_rn(c3);
                __half l0 = __float2half_rn(c0 - __half2float(h0));
                __half l1 = __float2half_rn(c1 - __half2float(h1));
                __half l2 = __float2half_rn(c2 - __half2float(h2));
                __half l3 = __float2half_rn(c3 - __half2float(h3));
                *reinterpret_cast<unsigned*>(&Ch[(long)row * ldc + col])       = packh(h0, h1);
                *reinterpret_cast<unsigned*>(&Cl[(long)row * ldc + col])       = packh(l0, l1);
                *reinterpret_cast<unsigned*>(&Ch[(long)(row + 8) * ldc + col]) = packh(h2, h3);
                *reinterpret_cast<unsigned*>(&Cl[(long)(row + 8) * ldc + col]) = packh(l2, l3);
            } else {
                const int bb = row >> 12;
                const int s  = row & 4095;
                __half* Cp = Ch + (long)bb * EMB * SEQ + s;
                Cp[(long)col * SEQ]           = __float2half_rn(c0);
                Cp[(long)(col + 1) * SEQ]     = __float2half_rn(c1);
                Cp[(long)col * SEQ + 8]       = __float2half_rn(c2);
                Cp[(long)(col + 1) * SEQ + 8] = __float2half_rn(c3);
            }
        }
    }
}

// ===========================================================================
// AV GEMM x1 (single fp16 in, fp32 out) — validated kernel, 2 CTAs/SM.
// ===========================================================================
#define GTILE_B  18432
#define H1STAGE_B (2 * GTILE_B)
#define H1SMEM    (2 * H1STAGE_B)            // 73728 B

__global__ void __launch_bounds__(512)
gemm_h1_nt(const __half* __restrict__ A, const __half* __restrict__ B,
           float* __restrict__ C, int K, int lda, int ldb, int ldc,
           long sA, long sB, long sC)
{
    extern __shared__ unsigned su[];

    const int bz = blockIdx.z;
    A += (long)bz * sA;
    B += (long)bz * sB;
    C += (long)bz * sC;

    const int tid  = threadIdx.x;
    const int lane = tid & 31;
    const int wid  = tid >> 5;
    const int wm   = (wid & 3) * 32;
    const int wn   = (wid >> 2) * 32;
    const int m0   = blockIdx.y * 128;
    const int n0   = blockIdx.x * 128;

    unsigned smemU;
    asm("{ .reg .u64 t; cvta.to.shared.u64 t, %1; cvt.u32.u64 %0, t; }"
        : "=r"(smemU) : "l"(su));

    const int crow = tid >> 2;
    const int cc   = (tid & 3) * 8;
    const unsigned dsto = (unsigned)(crow * 144 + cc * 2);

    auto stageCopy = [&](int buf, int kt) {
        const unsigned base = smemU + (unsigned)buf * H1STAGE_B;
        const long ao = (long)(m0 + crow) * lda + (long)kt * 64 + cc;
        const long bo = (long)(n0 + crow) * ldb + (long)kt * 64 + cc;
        cp16(base + 0 * GTILE_B + dsto,      A + ao);
        cp16(base + 0 * GTILE_B + dsto + 64, A + ao + 32);
        cp16(base + 1 * GTILE_B + dsto,      B + bo);
        cp16(base + 1 * GTILE_B + dsto + 64, B + bo + 32);
    };

    float acc[2][4][4];
#pragma unroll
    for (int i = 0; i < 2; i++)
#pragma unroll
        for (int j = 0; j < 4; j++)
#pragma unroll
            for (int r = 0; r < 4; r++) acc[i][j][r] = 0.f;

    const int r8 = lane & 7;
    const int hb = (lane >> 3) & 1;
    const int hf = lane >> 4;
    unsigned aOff[2], bOff[2];
#pragma unroll
    for (int mi = 0; mi < 2; mi++)
        aOff[mi] = ((wm + mi * 16 + r8 + hb * 8) * 72 + hf * 8) * 2;
#pragma unroll
    for (int p = 0; p < 2; p++)
        bOff[p] = ((wn + p * 16 + r8 + hf * 8) * 72) * 2 + hb * 16;

    const int niter = K >> 6;

    stageCopy(0, 0);
    asm volatile("cp.async.commit_group;");

    for (int it = 0; it < niter; it++) {
        if (it + 1 < niter) {
            stageCopy((it + 1) & 1, it + 1);
            asm volatile("cp.async.commit_group;");
            asm volatile("cp.async.wait_group 1;");
        } else {
            asm volatile("cp.async.wait_group 0;");
        }
        __syncthreads();

        const unsigned stB = smemU + (unsigned)((it & 1) * H1STAGE_B);
        const unsigned aH = stB;
        const unsigned bH = stB + GTILE_B;

#pragma unroll
        for (int ks = 0; ks < 4; ks++) {
            unsigned aF[2][4];
            unsigned bF[4][2];
#pragma unroll
            for (int mi = 0; mi < 2; mi++) {
                asm volatile("ldmatrix.sync.aligned.m8n8.x4.shared.b16 {%0,%1,%2,%3}, [%4];"
                    : "=r"(aF[mi][0]), "=r"(aF[mi][1]), "=r"(aF[mi][2]), "=r"(aF[mi][3])
                    : "r"(aH + aOff[mi] + ks * 32));
            }
#pragma unroll
            for (int p = 0; p < 2; p++) {
                unsigned q0, q1, q2, q3;
                asm volatile("ldmatrix.sync.aligned.m8n8.x4.shared.b16 {%0,%1,%2,%3}, [%4];"
                    : "=r"(q0), "=r"(q1), "=r"(q2), "=r"(q3)
                    : "r"(bH + bOff[p] + ks * 32));
                bF[2 * p][0] = q0; bF[2 * p][1] = q1;
                bF[2 * p + 1][0] = q2; bF[2 * p + 1][1] = q3;
            }
#pragma unroll
            for (int mi = 0; mi < 2; mi++)
#pragma unroll
                for (int nj = 0; nj < 4; nj++)
                    MMAH(aF, bF, mi, nj, nj);
        }
        __syncthreads();
    }

    const int g = lane >> 2;
    const int t = lane & 3;
#pragma unroll
    for (int nj = 0; nj < 4; nj++) {
        const int col = n0 + wn + nj * 8 + t * 2;
#pragma unroll
        for (int mi = 0; mi < 2; mi++) {
            const int row = m0 + wm + mi * 16 + g;
            *reinterpret_cast<float2*>(&C[(long)row * ldc + col]) =
                make_float2(acc[mi][nj][0], acc[mi][nj][1]);
            *reinterpret_cast<float2*>(&C[(long)(row + 8) * ldc + col]) =
                make_float2(acc[mi][nj][2], acc[mi][nj][3]);
        }
    }
}

// ---------------------------------------------------------------------------
// Row softmax: fp32 scores -> single fp16 attn. 256 thr / 4096 cols.
// ---------------------------------------------------------------------------
__global__ void __launch_bounds__(256)
softmax_h(const float* __restrict__ S, __half* __restrict__ P)
{
    const long row = blockIdx.x;
    const float* p = S + row * (long)SEQ;
    const int tid  = threadIdx.x;
    const int lane = tid & 31;
    const int wid  = tid >> 5;

    float vals[16];
    float m = -3.0e38f;
#pragma unroll
    for (int i = 0; i < 4; i++) {
        float4 v = reinterpret_cast<const float4*>(p)[tid + i * 256];
        vals[i * 4 + 0] = v.x; vals[i * 4 + 1] = v.y;
        vals[i * 4 + 2] = v.z; vals[i * 4 + 3] = v.w;
        m = fmaxf(m, fmaxf(fmaxf(v.x, v.y), fmaxf(v.z, v.w)));
    }

    __shared__ float red[8];
#pragma unroll
    for (int off = 16; off > 0; off >>= 1)
        m = fmaxf(m, __shfl_xor_sync(0xffffffffu, m, off));
    if (lane == 0) red[wid] = m;
    __syncthreads();
    float mAll = red[0];
#pragma unroll
    for (int w = 1; w < 8; w++) mAll = fmaxf(mAll, red[w]);
    __syncthreads();

    float s = 0.f;
#pragma unroll
    for (int i = 0; i < 16; i++) {
        vals[i] = __expf(vals[i] - mAll);
        s += vals[i];
    }
#pragma unroll
    for (int off = 16; off > 0; off >>= 1)
        s += __shfl_xor_sync(0xffffffffu, s, off);
    if (lane == 0) red[wid] = s;
    __syncthreads();
    float sAll = 0.f;
#pragma unroll
    for (int w = 0; w < 8; w++) sAll += red[w];
    const float inv = 1.0f / sAll;

    uint2* ph = reinterpret_cast<uint2*>(P + row * (long)SEQ);
#pragma unroll
    for (int i = 0; i < 4; i++) {
        unsigned h0 = packh(__float2half_rn(vals[i * 4 + 0] * inv),
                            __float2half_rn(vals[i * 4 + 1] * inv));
        unsigned h1 = packh(__float2half_rn(vals[i * 4 + 2] * inv),
                            __float2half_rn(vals[i * 4 + 3] * inv));
        ph[tid + i * 256] = make_uint2(h0, h1);
    }
}

// ---------------------------------------------------------------------------
extern "C" void kernel_launch(void* const* d_in, const int* in_sizes, int n_in,
                              void* d_out, int out_size)
{
    const float* q_in = (const float*)d_in[0];
    const float* k_in = (const float*)d_in[1];
    const float* v_in = (const float*)d_in[2];
    const float* Wq   = (const float*)d_in[3];
    const float* bq   = (const float*)d_in[4];
    const float* Wk   = (const float*)d_in[5];
    const float* bk   = (const float*)d_in[6];
    const float* Wv   = (const float*)d_in[7];
    const float* bv   = (const float*)d_in[8];
    float* out = (float*)d_out;

    float* gs;
    __half *xqh, *xql, *xkh, *xkl, *xvh, *xvl;
    __half *wqh, *wql, *wkh, *wkl, *wvh, *wvl;
    __half *qh, *ql, *kh, *kl, *vt, *pp;
    cudaGetSymbolAddress((void**)&gs, g_s);
    cudaGetSymbolAddress((void**)&xqh, g_xqh); cudaGetSymbolAddress((void**)&xql, g_xql);
    cudaGetSymbolAddress((void**)&xkh, g_xkh); cudaGetSymbolAddress((void**)&xkl, g_xkl);
    cudaGetSymbolAddress((void**)&xvh, g_xvh); cudaGetSymbolAddress((void**)&xvl, g_xvl);
    cudaGetSymbolAddress((void**)&wqh, g_wqh); cudaGetSymbolAddress((void**)&wql, g_wql);
    cudaGetSymbolAddress((void**)&wkh, g_wkh); cudaGetSymbolAddress((void**)&wkl, g_wkl);
    cudaGetSymbolAddress((void**)&wvh, g_wvh); cudaGetSymbolAddress((void**)&wvl, g_wvl);
    cudaGetSymbolAddress((void**)&qh, g_qh);   cudaGetSymbolAddress((void**)&ql, g_ql);
    cudaGetSymbolAddress((void**)&kh, g_kh);   cudaGetSymbolAddress((void**)&kl, g_kl);
    cudaGetSymbolAddress((void**)&vt, g_vt);   cudaGetSymbolAddress((void**)&pp, g_p);

    static cudaStream_t sSide = nullptr;
    static cudaEvent_t evFork = nullptr, evV = nullptr;
    static bool attrDone = false;
    if (!attrDone) {
        cudaFuncSetAttribute(gemm_h2<0>, cudaFuncAttributeMaxDynamicSharedMemorySize, H2SMEM);
        cudaFuncSetAttribute(gemm_h2<1>, cudaFuncAttributeMaxDynamicSharedMemorySize, H2SMEM);
        cudaFuncSetAttribute(gemm_h2<2>, cudaFuncAttributeMaxDynamicSharedMemorySize, H2SMEM);
        cudaFuncSetAttribute(gemm_h1_nt, cudaFuncAttributeMaxDynamicSharedMemorySize, H1SMEM);
        cudaStreamCreateWithFlags(&sSide, cudaStreamNonBlocking);
        cudaEventCreateWithFlags(&evFork, cudaEventDisableTiming);
        cudaEventCreateWithFlags(&evV, cudaEventDisableTiming);
        attrDone = true;
    }

    const int NX4 = BATCH * SEQ * EMB / 4;   // 2M float4
    const int NW4 = EMB * EMB / 4;           // 64K float4

    // fork: V-projection chain on side stream (AV is sole consumer of vt)
    cudaEventRecord(evFork, 0);
    cudaStreamWaitEvent(sSide, evFork, 0);

    split_f32<<<2048, 256, 0, sSide>>>(v_in, xvh, xvl, NX4);
    split_f32<<<256, 256, 0, sSide>>>(Wv, wvh, wvl, NW4);
    {
        dim3 grd(EMB / 128, (BATCH * SEQ) / 128, 1);
        gemm_h2<2><<<grd, 512, H2SMEM, sSide>>>(xvh, xvl, wvh, wvl, bv,
                                                nullptr, vt, nullptr,
                                                EMB, EMB, EMB, SEQ, 0, 0, 0);
    }
    cudaEventRecord(evV, sSide);

    // main chain
    split_f32<<<2048, 256>>>(q_in, xqh, xql, NX4);
    split_f32<<<2048, 256>>>(k_in, xkh, xkl, NX4);
    split_f32<<<256, 256>>>(Wq, wqh, wql, NW4);
    split_f32<<<256, 256>>>(Wk, wkh, wkl, NW4);

    {
        dim3 grd(EMB / 128, (BATCH * SEQ) / 128, 1);
        gemm_h2<1><<<grd, 512, H2SMEM>>>(xqh, xql, wqh, wql, bq,
                                         nullptr, qh, ql, EMB, EMB, EMB, EMB, 0, 0, 0);
        gemm_h2<1><<<grd, 512, H2SMEM>>>(xkh, xkl, wkh, wkl, bk,
                                         nullptr, kh, kl, EMB, EMB, EMB, EMB, 0, 0, 0);
    }

    // scores[b] = q[b] @ k[b]^T  (h2, fp32 out)
    {
        dim3 grd(SEQ / 128, SEQ / 128, BATCH);
        gemm_h2<0><<<grd, 512, H2SMEM>>>(qh, ql, kh, kl, nullptr,
                                         gs, nullptr, nullptr, EMB, EMB, EMB, SEQ,
                                         (long)SEQ * EMB, (long)SEQ * EMB,
                                         (long)SEQ * SEQ);
    }

    // softmax -> single fp16 attn
    softmax_h<<<BATCH * SEQ, 256>>>(gs, pp);

    // join: AV needs vt from side stream
    cudaStreamWaitEvent(0, evV, 0);

    // out[b] = attn[b] @ v[b]  (h1)
    {
        dim3 grd(EMB / 128, SEQ / 128, BATCH);
        gemm_h1_nt<<<grd, 512, H1SMEM>>>(pp, vt, out, SEQ, SEQ, SEQ, EMB,
                                         (long)SEQ * SEQ, (long)EMB * SEQ,
                                         (long)SEQ * EMB);
    }
}

// round 17
// speedup vs baseline: 1.1867x; 1.0291x over previous
#include <cuda_runtime.h>
#include <cuda_fp16.h>
#include <math.h>

#define BATCH 4
#define SEQ   4096
#define EMB   512

// Scratch (__device__ globals: sanctioned, no runtime allocation)
__device__ float g_s[(size_t)BATCH * SEQ * SEQ];                  // 256 MB scores
__device__ __half g_xqh[BATCH * SEQ * EMB], g_xql[BATCH * SEQ * EMB];
__device__ __half g_xkh[BATCH * SEQ * EMB], g_xkl[BATCH * SEQ * EMB];
__device__ __half g_xvh[BATCH * SEQ * EMB], g_xvl[BATCH * SEQ * EMB];
__device__ __half g_wqh[EMB * EMB], g_wql[EMB * EMB];
__device__ __half g_wkh[EMB * EMB], g_wkl[EMB * EMB];
__device__ __half g_wvh[EMB * EMB], g_wvl[EMB * EMB];
__device__ __half g_qh[BATCH * SEQ * EMB], g_ql[BATCH * SEQ * EMB];
__device__ __half g_kh[BATCH * SEQ * EMB], g_kl[BATCH * SEQ * EMB];
__device__ __half g_vt[BATCH * SEQ * EMB];                        // [b][e][s]
__device__ __half g_p [(size_t)BATCH * SEQ * SEQ];                // 128 MB attn

__device__ __forceinline__ unsigned packh(__half a, __half b) {
    return ((unsigned)__half_as_ushort(b) << 16) | __half_as_ushort(a);
}
__device__ __forceinline__ void cp16(unsigned dst, const void* src) {
    asm volatile("cp.async.cg.shared.global [%0], [%1], 16;" :: "r"(dst), "l"(src));
}

#define MMAH(aa, bb, mi, aj, bj)                                              \
    asm volatile(                                                             \
        "mma.sync.aligned.m16n8k16.row.col.f32.f16.f16.f32 "                  \
        "{%0,%1,%2,%3}, {%4,%5,%6,%7}, {%8,%9}, {%0,%1,%2,%3};"               \
        : "+f"(acc[mi][aj][0]), "+f"(acc[mi][aj][1]),                         \
          "+f"(acc[mi][aj][2]), "+f"(acc[mi][aj][3])                          \
        : "r"(aa[mi][0]), "r"(aa[mi][1]), "r"(aa[mi][2]), "r"(aa[mi][3]),     \
          "r"(bb[bj][0]), "r"(bb[bj][1]))

// ---------------------------------------------------------------------------
// Elementwise fp32 -> split fp16 (h = rn(x), l = rn(x - h)), float4-wide.
// ---------------------------------------------------------------------------
__global__ void __launch_bounds__(256)
split_f32(const float* __restrict__ src, __half* __restrict__ H,
          __half* __restrict__ L, int n4)
{
    const int stride = gridDim.x * blockDim.x;
    for (int i = blockIdx.x * blockDim.x + threadIdx.x; i < n4; i += stride) {
        float4 v = reinterpret_cast<const float4*>(src)[i];
        __half h0 = __float2half_rn(v.x), h1 = __float2half_rn(v.y);
        __half h2 = __float2half_rn(v.z), h3 = __float2half_rn(v.w);
        __half l0 = __float2half_rn(v.x - __half2float(h0));
        __half l1 = __float2half_rn(v.y - __half2float(h1));
        __half l2 = __float2half_rn(v.z - __half2float(h2));
        __half l3 = __float2half_rn(v.w - __half2float(h3));
        reinterpret_cast<uint2*>(H)[i] = make_uint2(packh(h0, h1), packh(h2, h3));
        reinterpret_cast<uint2*>(L)[i] = make_uint2(packh(l0, l1), packh(l2, l3));
    }
}

// ===========================================================================
// h2 GEMM core (validated round-16): CTA 128x128, BK=32, 512 threads,
// register-lean hl/hh/lh pass ordering, __launch_bounds__(512,2).
// EPI: 0 = fp32 C (score), 1 = split fp16 + bias (Q/K proj),
//      2 = transposed single fp16 + bias (V proj).
// ===========================================================================
#define H2TILE_B  10240
#define H2STAGE_B (4 * H2TILE_B)
#define H2SMEM    (2 * H2STAGE_B)            // 81920 B

template <int EPI>
__global__ void __launch_bounds__(512, 2)
gemm_h2(const __half* __restrict__ Ah, const __half* __restrict__ Al,
        const __half* __restrict__ Bh, const __half* __restrict__ Bl,
        const float* __restrict__ bias,
        float* __restrict__ Cf, __half* __restrict__ Ch, __half* __restrict__ Cl,
        int K, int lda, int ldb, int ldc,
        long sA, long sB, long sC)
{
    extern __shared__ unsigned su[];

    const int bz = blockIdx.z;
    Ah += (long)bz * sA; Al += (long)bz * sA;
    Bh += (long)bz * sB; Bl += (long)bz * sB;

    const int tid  = threadIdx.x;
    const int lane = tid & 31;
    const int wid  = tid >> 5;
    const int wm   = (wid & 3) * 32;
    const int wn   = (wid >> 2) * 32;
    const int m0   = blockIdx.y * 128;
    const int n0   = blockIdx.x * 128;

    unsigned smemU;
    asm("{ .reg .u64 t; cvta.to.shared.u64 t, %1; cvt.u32.u64 %0, t; }"
        : "=r"(smemU) : "l"(su));

    const int crow = tid >> 2;
    const int cch  = tid & 3;
    const unsigned dsto = (unsigned)(crow * 80 + cch * 16);

    auto stageCopy = [&](int buf, int kt) {
        const unsigned base = smemU + (unsigned)buf * H2STAGE_B;
        const long ao = (long)(m0 + crow) * lda + (long)kt * 32 + cch * 8;
        const long bo = (long)(n0 + crow) * ldb + (long)kt * 32 + cch * 8;
        cp16(base + 0 * H2TILE_B + dsto, Ah + ao);
        cp16(base + 1 * H2TILE_B + dsto, Bh + bo);
        cp16(base + 2 * H2TILE_B + dsto, Al + ao);
        cp16(base + 3 * H2TILE_B + dsto, Bl + bo);
    };

    float acc[2][4][4];
#pragma unroll
    for (int i = 0; i < 2; i++)
#pragma unroll
        for (int j = 0; j < 4; j++)
#pragma unroll
            for (int r = 0; r < 4; r++) acc[i][j][r] = 0.f;

    const int r8 = lane & 7;
    const int hb = (lane >> 3) & 1;
    const int hf = lane >> 4;
    unsigned aOff[2], bOff[2];
#pragma unroll
    for (int mi = 0; mi < 2; mi++)
        aOff[mi] = ((wm + mi * 16 + r8 + hb * 8) * 40 + hf * 8) * 2;
#pragma unroll
    for (int p = 0; p < 2; p++)
        bOff[p] = ((wn + p * 16 + r8 + hf * 8) * 40) * 2 + hb * 16;

    const int niter = K >> 5;

    stageCopy(0, 0);
    asm volatile("cp.async.commit_group;");

    for (int it = 0; it < niter; it++) {
        if (it + 1 < niter) {
            stageCopy((it + 1) & 1, it + 1);
            asm volatile("cp.async.commit_group;");
            asm volatile("cp.async.wait_group 1;");
        } else {
            asm volatile("cp.async.wait_group 0;");
        }
        __syncthreads();

        const unsigned stB = smemU + (unsigned)((it & 1) * H2STAGE_B);
        const unsigned aH = stB;
        const unsigned bH = stB + H2TILE_B;
        const unsigned aL = stB + 2u * H2TILE_B;
        const unsigned bL = stB + 3u * H2TILE_B;

#pragma unroll
        for (int ks = 0; ks < 2; ks++) {
            unsigned aF[2][4];
            unsigned bF[4][2];

            // pass 1: aFh x bFl
#pragma unroll
            for (int mi = 0; mi < 2; mi++)
                asm volatile("ldmatrix.sync.aligned.m8n8.x4.shared.b16 {%0,%1,%2,%3}, [%4];"
                    : "=r"(aF[mi][0]), "=r"(aF[mi][1]), "=r"(aF[mi][2]), "=r"(aF[mi][3])
                    : "r"(aH + aOff[mi] + ks * 32));
#pragma unroll
            for (int p = 0; p < 2; p++) {
                unsigned q0, q1, q2, q3;
                asm volatile("ldmatrix.sync.aligned.m8n8.x4.shared.b16 {%0,%1,%2,%3}, [%4];"
                    : "=r"(q0), "=r"(q1), "=r"(q2), "=r"(q3)
                    : "r"(bL + bOff[p] + ks * 32));
                bF[2 * p][0] = q0; bF[2 * p][1] = q1;
                bF[2 * p + 1][0] = q2; bF[2 * p + 1][1] = q3;
            }
#pragma unroll
            for (int mi = 0; mi < 2; mi++)
#pragma unroll
                for (int nj = 0; nj < 4; nj++)
                    MMAH(aF, bF, mi, nj, nj);

            // pass 2: aFh x bFh (reload B)
#pragma unroll
            for (int p = 0; p < 2; p++) {
                unsigned q0, q1, q2, q3;
                asm volatile("ldmatrix.sync.aligned.m8n8.x4.shared.b16 {%0,%1,%2,%3}, [%4];"
                    : "=r"(q0), "=r"(q1), "=r"(q2), "=r"(q3)
                    : "r"(bH + bOff[p] + ks * 32));
                bF[2 * p][0] = q0; bF[2 * p][1] = q1;
                bF[2 * p + 1][0] = q2; bF[2 * p + 1][1] = q3;
            }
#pragma unroll
            for (int mi = 0; mi < 2; mi++)
#pragma unroll
                for (int nj = 0; nj < 4; nj++)
                    MMAH(aF, bF, mi, nj, nj);

            // pass 3: aFl x bFh (reload A)
#pragma unroll
            for (int mi = 0; mi < 2; mi++)
                asm volatile("ldmatrix.sync.aligned.m8n8.x4.shared.b16 {%0,%1,%2,%3}, [%4];"
                    : "=r"(aF[mi][0]), "=r"(aF[mi][1]), "=r"(aF[mi][2]), "=r"(aF[mi][3])
                    : "r"(aL + aOff[mi] + ks * 32));
#pragma unroll
            for (int mi = 0; mi < 2; mi++)
#pragma unroll
                for (int nj = 0; nj < 4; nj++)
                    MMAH(aF, bF, mi, nj, nj);
        }
        __syncthreads();
    }

    // epilogue
    const int g = lane >> 2;
    const int t = lane & 3;
#pragma unroll
    for (int nj = 0; nj < 4; nj++) {
        const int col = n0 + wn + nj * 8 + t * 2;
        float b0 = 0.f, b1 = 0.f;
        if (EPI != 0) { b0 = bias[col]; b1 = bias[col + 1]; }
#pragma unroll
        for (int mi = 0; mi < 2; mi++) {
            const int row = m0 + wm + mi * 16 + g;
            float c0 = acc[mi][nj][0] + b0;
            float c1 = acc[mi][nj][1] + b1;
            float c2 = acc[mi][nj][2] + b0;
            float c3 = acc[mi][nj][3] + b1;
            if (EPI == 0) {
                float* Cp = Cf + (long)bz * sC;
                *reinterpret_cast<float2*>(&Cp[(long)row * ldc + col]) = make_float2(c0, c1);
                *reinterpret_cast<float2*>(&Cp[(long)(row + 8) * ldc + col]) = make_float2(c2, c3);
            } else if (EPI == 1) {
                __half h0 = __float2half_rn(c0), h1 = __float2half_rn(c1);
                __half h2 = __float2half_rn(c2), h3 = __float2half_rn(c3);
                __half l0 = __float2half_rn(c0 - __half2float(h0));
                __half l1 = __float2half_rn(c1 - __half2float(h1));
                __half l2 = __float2half_rn(c2 - __half2float(h2));
                __half l3 = __float2half_rn(c3 - __half2float(h3));
                *reinterpret_cast<unsigned*>(&Ch[(long)row * ldc + col])       = packh(h0, h1);
                *reinterpret_cast<unsigned*>(&Cl[(long)row * ldc + col])       = packh(l0, l1);
                *reinterpret_cast<unsigned*>(&Ch[(long)(row + 8) * ldc + col]) = packh(h2, h3);
                *reinterpret_cast<unsigned*>(&Cl[(long)(row + 8) * ldc + col]) = packh(l2, l3);
            } else {
                const int bb = row >> 12;
                const int s  = row & 4095;
                __half* Cp = Ch + (long)bb * EMB * SEQ + s;
                Cp[(long)col * SEQ]           = __float2half_rn(c0);
                Cp[(long)(col + 1) * SEQ]     = __float2half_rn(c1);
                Cp[(long)col * SEQ + 8]       = __float2half_rn(c2);
                Cp[(long)(col + 1) * SEQ + 8] = __float2half_rn(c3);
            }
        }
    }
}

// ===========================================================================
// AV GEMM x1 (single fp16 in, fp32 out) — validated kernel, 2 CTAs/SM.
// ===========================================================================
#define GTILE_B  18432
#define H1STAGE_B (2 * GTILE_B)
#define H1SMEM    (2 * H1STAGE_B)            // 73728 B

__global__ void __launch_bounds__(512)
gemm_h1_nt(const __half* __restrict__ A, const __half* __restrict__ B,
           float* __restrict__ C, int K, int lda, int ldb, int ldc,
           long sA, long sB, long sC)
{
    extern __shared__ unsigned su[];

    const int bz = blockIdx.z;
    A += (long)bz * sA;
    B += (long)bz * sB;
    C += (long)bz * sC;

    const int tid  = threadIdx.x;
    const int lane = tid & 31;
    const int wid  = tid >> 5;
    const int wm   = (wid & 3) * 32;
    const int wn   = (wid >> 2) * 32;
    const int m0   = blockIdx.y * 128;
    const int n0   = blockIdx.x * 128;

    unsigned smemU;
    asm("{ .reg .u64 t; cvta.to.shared.u64 t, %1; cvt.u32.u64 %0, t; }"
        : "=r"(smemU) : "l"(su));

    const int crow = tid >> 2;
    const int cc   = (tid & 3) * 8;
    const unsigned dsto = (unsigned)(crow * 144 + cc * 2);

    auto stageCopy = [&](int buf, int kt) {
        const unsigned base = smemU + (unsigned)buf * H1STAGE_B;
        const long ao = (long)(m0 + crow) * lda + (long)kt * 64 + cc;
        const long bo = (long)(n0 + crow) * ldb + (long)kt * 64 + cc;
        cp16(base + 0 * GTILE_B + dsto,      A + ao);
        cp16(base + 0 * GTILE_B + dsto + 64, A + ao + 32);
        cp16(base + 1 * GTILE_B + dsto,      B + bo);
        cp16(base + 1 * GTILE_B + dsto + 64, B + bo + 32);
    };

    float acc[2][4][4];
#pragma unroll
    for (int i = 0; i < 2; i++)
#pragma unroll
        for (int j = 0; j < 4; j++)
#pragma unroll
            for (int r = 0; r < 4; r++) acc[i][j][r] = 0.f;

    const int r8 = lane & 7;
    const int hb = (lane >> 3) & 1;
    const int hf = lane >> 4;
    unsigned aOff[2], bOff[2];
#pragma unroll
    for (int mi = 0; mi < 2; mi++)
        aOff[mi] = ((wm + mi * 16 + r8 + hb * 8) * 72 + hf * 8) * 2;
#pragma unroll
    for (int p = 0; p < 2; p++)
        bOff[p] = ((wn + p * 16 + r8 + hf * 8) * 72) * 2 + hb * 16;

    const int niter = K >> 6;

    stageCopy(0, 0);
    asm volatile("cp.async.commit_group;");

    for (int it = 0; it < niter; it++) {
        if (it + 1 < niter) {
            stageCopy((it + 1) & 1, it + 1);
            asm volatile("cp.async.commit_group;");
            asm volatile("cp.async.wait_group 1;");
        } else {
            asm volatile("cp.async.wait_group 0;");
        }
        __syncthreads();

        const unsigned stB = smemU + (unsigned)((it & 1) * H1STAGE_B);
        const unsigned aH = stB;
        const unsigned bH = stB + GTILE_B;

#pragma unroll
        for (int ks = 0; ks < 4; ks++) {
            unsigned aF[2][4];
            unsigned bF[4][2];
#pragma unroll
            for (int mi = 0; mi < 2; mi++) {
                asm volatile("ldmatrix.sync.aligned.m8n8.x4.shared.b16 {%0,%1,%2,%3}, [%4];"
                    : "=r"(aF[mi][0]), "=r"(aF[mi][1]), "=r"(aF[mi][2]), "=r"(aF[mi][3])
                    : "r"(aH + aOff[mi] + ks * 32));
            }
#pragma unroll
            for (int p = 0; p < 2; p++) {
                unsigned q0, q1, q2, q3;
                asm volatile("ldmatrix.sync.aligned.m8n8.x4.shared.b16 {%0,%1,%2,%3}, [%4];"
                    : "=r"(q0), "=r"(q1), "=r"(q2), "=r"(q3)
                    : "r"(bH + bOff[p] + ks * 32));
                bF[2 * p][0] = q0; bF[2 * p][1] = q1;
                bF[2 * p + 1][0] = q2; bF[2 * p + 1][1] = q3;
            }
#pragma unroll
            for (int mi = 0; mi < 2; mi++)
#pragma unroll
                for (int nj = 0; nj < 4; nj++)
                    MMAH(aF, bF, mi, nj, nj);
        }
        __syncthreads();
    }

    const int g = lane >> 2;
    const int t = lane & 3;
#pragma unroll
    for (int nj = 0; nj < 4; nj++) {
        const int col = n0 + wn + nj * 8 + t * 2;
#pragma unroll
        for (int mi = 0; mi < 2; mi++) {
            const int row = m0 + wm + mi * 16 + g;
            *reinterpret_cast<float2*>(&C[(long)row * ldc + col]) =
                make_float2(acc[mi][nj][0], acc[mi][nj][1]);
            *reinterpret_cast<float2*>(&C[(long)(row + 8) * ldc + col]) =
                make_float2(acc[mi][nj][2], acc[mi][nj][3]);
        }
    }
}

// ---------------------------------------------------------------------------
// Row softmax: fp32 scores -> single fp16 attn. 256 thr / 4096 cols.
// ---------------------------------------------------------------------------
__global__ void __launch_bounds__(256)
softmax_h(const float* __restrict__ S, __half* __restrict__ P)
{
    const long row = blockIdx.x;
    const float* p = S + row * (long)SEQ;
    const int tid  = threadIdx.x;
    const int lane = tid & 31;
    const int wid  = tid >> 5;

    float vals[16];
    float m = -3.0e38f;
#pragma unroll
    for (int i = 0; i < 4; i++) {
        float4 v = reinterpret_cast<const float4*>(p)[tid + i * 256];
        vals[i * 4 + 0] = v.x; vals[i * 4 + 1] = v.y;
        vals[i * 4 + 2] = v.z; vals[i * 4 + 3] = v.w;
        m = fmaxf(m, fmaxf(fmaxf(v.x, v.y), fmaxf(v.z, v.w)));
    }

    __shared__ float red[8];
#pragma unroll
    for (int off = 16; off > 0; off >>= 1)
        m = fmaxf(m, __shfl_xor_sync(0xffffffffu, m, off));
    if (lane == 0) red[wid] = m;
    __syncthreads();
    float mAll = red[0];
#pragma unroll
    for (int w = 1; w < 8; w++) mAll = fmaxf(mAll, red[w]);
    __syncthreads();

    float s = 0.f;
#pragma unroll
    for (int i = 0; i < 16; i++) {
        vals[i] = __expf(vals[i] - mAll);
        s += vals[i];
    }
#pragma unroll
    for (int off = 16; off > 0; off >>= 1)
        s += __shfl_xor_sync(0xffffffffu, s, off);
    if (lane == 0) red[wid] = s;
    __syncthreads();
    float sAll = 0.f;
#pragma unroll
    for (int w = 0; w < 8; w++) sAll += red[w];
    const float inv = 1.0f / sAll;

    uint2* ph = reinterpret_cast<uint2*>(P + row * (long)SEQ);
#pragma unroll
    for (int i = 0; i < 4; i++) {
        unsigned h0 = packh(__float2half_rn(vals[i * 4 + 0] * inv),
                            __float2half_rn(vals[i * 4 + 1] * inv));
        unsigned h1 = packh(__float2half_rn(vals[i * 4 + 2] * inv),
                            __float2half_rn(vals[i * 4 + 3] * inv));
        ph[tid + i * 256] = make_uint2(h0, h1);
    }
}

// ---------------------------------------------------------------------------
extern "C" void kernel_launch(void* const* d_in, const int* in_sizes, int n_in,
                              void* d_out, int out_size)
{
    const float* q_in = (const float*)d_in[0];
    const float* k_in = (const float*)d_in[1];
    const float* v_in = (const float*)d_in[2];
    const float* Wq   = (const float*)d_in[3];
    const float* bq   = (const float*)d_in[4];
    const float* Wk   = (const float*)d_in[5];
    const float* bk   = (const float*)d_in[6];
    const float* Wv   = (const float*)d_in[7];
    const float* bv   = (const float*)d_in[8];
    float* out = (float*)d_out;

    float* gs;
    __half *xqh, *xql, *xkh, *xkl, *xvh, *xvl;
    __half *wqh, *wql, *wkh, *wkl, *wvh, *wvl;
    __half *qh, *ql, *kh, *kl, *vt, *pp;
    cudaGetSymbolAddress((void**)&gs, g_s);
    cudaGetSymbolAddress((void**)&xqh, g_xqh); cudaGetSymbolAddress((void**)&xql, g_xql);
    cudaGetSymbolAddress((void**)&xkh, g_xkh); cudaGetSymbolAddress((void**)&xkl, g_xkl);
    cudaGetSymbolAddress((void**)&xvh, g_xvh); cudaGetSymbolAddress((void**)&xvl, g_xvl);
    cudaGetSymbolAddress((void**)&wqh, g_wqh); cudaGetSymbolAddress((void**)&wql, g_wql);
    cudaGetSymbolAddress((void**)&wkh, g_wkh); cudaGetSymbolAddress((void**)&wkl, g_wkl);
    cudaGetSymbolAddress((void**)&wvh, g_wvh); cudaGetSymbolAddress((void**)&wvl, g_wvl);
    cudaGetSymbolAddress((void**)&qh, g_qh);   cudaGetSymbolAddress((void**)&ql, g_ql);
    cudaGetSymbolAddress((void**)&kh, g_kh);   cudaGetSymbolAddress((void**)&kl, g_kl);
    cudaGetSymbolAddress((void**)&vt, g_vt);   cudaGetSymbolAddress((void**)&pp, g_p);

    static cudaStream_t s2 = nullptr, s3 = nullptr;
    static cudaEvent_t evFork = nullptr, evK = nullptr, evV = nullptr;
    static cudaEvent_t evS[BATCH], evP[BATCH], evA = nullptr;
    static bool initDone = false;
    if (!initDone) {
        cudaFuncSetAttribute(gemm_h2<0>, cudaFuncAttributeMaxDynamicSharedMemorySize, H2SMEM);
        cudaFuncSetAttribute(gemm_h2<1>, cudaFuncAttributeMaxDynamicSharedMemorySize, H2SMEM);
        cudaFuncSetAttribute(gemm_h2<2>, cudaFuncAttributeMaxDynamicSharedMemorySize, H2SMEM);
        cudaFuncSetAttribute(gemm_h1_nt, cudaFuncAttributeMaxDynamicSharedMemorySize, H1SMEM);
        cudaStreamCreateWithFlags(&s2, cudaStreamNonBlocking);
        cudaStreamCreateWithFlags(&s3, cudaStreamNonBlocking);
        cudaEventCreateWithFlags(&evFork, cudaEventDisableTiming);
        cudaEventCreateWithFlags(&evK, cudaEventDisableTiming);
        cudaEventCreateWithFlags(&evV, cudaEventDisableTiming);
        for (int b = 0; b < BATCH; b++) {
            cudaEventCreateWithFlags(&evS[b], cudaEventDisableTiming);
            cudaEventCreateWithFlags(&evP[b], cudaEventDisableTiming);
        }
        cudaEventCreateWithFlags(&evA, cudaEventDisableTiming);
        initDone = true;
    }

    const int NX4 = BATCH * SEQ * EMB / 4;
    const int NW4 = EMB * EMB / 4;
    const long XB = (long)SEQ * EMB;        // per-batch x/q/k stride
    const long SB = (long)SEQ * SEQ;        // per-batch score/attn stride

    // fork
    cudaEventRecord(evFork, 0);
    cudaStreamWaitEvent(s2, evFork, 0);
    cudaStreamWaitEvent(s3, evFork, 0);

    // s3: V chain
    split_f32<<<2048, 256, 0, s3>>>(v_in, xvh, xvl, NX4);
    split_f32<<<256, 256, 0, s3>>>(Wv, wvh, wvl, NW4);
    {
        dim3 grd(EMB / 128, (BATCH * SEQ) / 128, 1);
        gemm_h2<2><<<grd, 512, H2SMEM, s3>>>(xvh, xvl, wvh, wvl, bv,
                                             nullptr, vt, nullptr,
                                             EMB, EMB, EMB, SEQ, 0, 0, 0);
    }
    cudaEventRecord(evV, s3);

    // s2: K chain
    split_f32<<<2048, 256, 0, s2>>>(k_in, xkh, xkl, NX4);
    split_f32<<<256, 256, 0, s2>>>(Wk, wkh, wkl, NW4);
    {
        dim3 grd(EMB / 128, (BATCH * SEQ) / 128, 1);
        gemm_h2<1><<<grd, 512, H2SMEM, s2>>>(xkh, xkl, wkh, wkl, bk,
                                             nullptr, kh, kl, EMB, EMB, EMB, EMB, 0, 0, 0);
    }
    cudaEventRecord(evK, s2);

    // main: Q chain
    split_f32<<<2048, 256>>>(q_in, xqh, xql, NX4);
    split_f32<<<256, 256>>>(Wq, wqh, wql, NW4);
    {
        dim3 grd(EMB / 128, (BATCH * SEQ) / 128, 1);
        gemm_h2<1><<<grd, 512, H2SMEM>>>(xqh, xql, wqh, wql, bq,
                                         nullptr, qh, ql, EMB, EMB, EMB, EMB, 0, 0, 0);
    }
    cudaStreamWaitEvent(0, evK, 0);

    // per-batch pipeline: score(b) on main; softmax(b) on s2; AV(b) on s3
    cudaStreamWaitEvent(s3, evV, 0);   // (no-op ordering: evV already on s3)
    for (int b = 0; b < BATCH; b++) {
        dim3 grdS(SEQ / 128, SEQ / 128, 1);
        gemm_h2<0><<<grdS, 512, H2SMEM>>>(qh + (long)b * XB, ql + (long)b * XB,
                                          kh + (long)b * XB, kl + (long)b * XB,
                                          nullptr, gs + (long)b * SB, nullptr, nullptr,
                                          EMB, EMB, EMB, SEQ, 0, 0, 0);
        cudaEventRecord(evS[b], 0);

        cudaStreamWaitEvent(s2, evS[b], 0);
        softmax_h<<<SEQ, 256, 0, s2>>>(gs + (long)b * SB, pp + (long)b * SB);
        cudaEventRecord(evP[b], s2);

        cudaStreamWaitEvent(s3, evP[b], 0);
        dim3 grdA(EMB / 128, SEQ / 128, 1);
        gemm_h1_nt<<<grdA, 512, H1SMEM, s3>>>(pp + (long)b * SB, vt + (long)b * XB,
                                              out + (long)b * XB,
                                              SEQ, SEQ, SEQ, EMB, 0, 0, 0);
    }
    cudaEventRecord(evA, s3);
    cudaStreamWaitEvent(0, evA, 0);     // join everything back to main stream
}